// round 3
// baseline (speedup 1.0000x reference)
#include <cuda_runtime.h>
#include <cstdint>
#include <math.h>

#define TT 8192
#define DD 2048
#define NE 8
#define FF 1408
#define MAX_ASSIGN 16896   /* 264 * 64 : 16384 assignments + per-expert 64-alignment padding */
#define MTILES 264
#define NT_GU 22           /* FF/64 */
#define NT_DN 32           /* DD/64 */
#define KC 32
#define SROW 36            /* padded smem row stride (words) */

// ---------------- scratch (device globals only; no allocation) ----------------
__device__ int   g_tk_idx[TT*2];
__device__ float g_tk_w[TT*2];
__device__ int   g_offs[NE+1];
__device__ int   g_tok[MAX_ASSIGN];
__device__ float g_twt[MAX_ASSIGN];
__device__ float g_act[(size_t)MAX_ASSIGN * FF];   // silu(h)*u, fp32

// ---------------- helpers ----------------
__device__ __forceinline__ uint32_t f2tf(float f){
    uint32_t u; asm("cvt.rna.tf32.f32 %0, %1;" : "=r"(u) : "f"(f)); return u;
}
__device__ __forceinline__ void mma_tf32(float c[4],
        uint32_t a0, uint32_t a1, uint32_t a2, uint32_t a3,
        uint32_t b0, uint32_t b1){
    asm volatile(
        "mma.sync.aligned.m16n8k8.row.col.f32.tf32.tf32.f32 "
        "{%0,%1,%2,%3}, {%4,%5,%6,%7}, {%8,%9}, {%0,%1,%2,%3};\n"
        : "+f"(c[0]), "+f"(c[1]), "+f"(c[2]), "+f"(c[3])
        : "r"(a0), "r"(a1), "r"(a2), "r"(a3), "r"(b0), "r"(b1));
}

// ---------------- router: logits, top-2, renormalized weights ----------------
__global__ void router_kernel(const float* __restrict__ x,
                              const float* __restrict__ gw,
                              float* __restrict__ logits){
    int warp = (blockIdx.x * blockDim.x + threadIdx.x) >> 5;
    int lane = threadIdx.x & 31;
    if (warp >= TT) return;
    const float* xr = x + (size_t)warp * DD;
    float acc[NE];
#pragma unroll
    for (int e = 0; e < NE; e++) acc[e] = 0.f;
    for (int c = lane * 4; c < DD; c += 128){
        float4 xv = *reinterpret_cast<const float4*>(xr + c);
#pragma unroll
        for (int e = 0; e < NE; e++){
            float4 gv = *reinterpret_cast<const float4*>(gw + e*DD + c);
            acc[e] += xv.x*gv.x; acc[e] += xv.y*gv.y;
            acc[e] += xv.z*gv.z; acc[e] += xv.w*gv.w;
        }
    }
#pragma unroll
    for (int e = 0; e < NE; e++){
#pragma unroll
        for (int o = 16; o > 0; o >>= 1) acc[e] += __shfl_xor_sync(0xffffffffu, acc[e], o);
    }
    if (lane == 0){
#pragma unroll
        for (int e = 0; e < NE; e++) logits[(size_t)warp*NE + e] = acc[e];
        int i0 = 0; float l0 = acc[0];
#pragma unroll
        for (int e = 1; e < NE; e++) if (acc[e] > l0){ l0 = acc[e]; i0 = e; }
        int i1 = -1; float l1 = -1e30f;
#pragma unroll
        for (int e = 0; e < NE; e++) if (e != i0 && acc[e] > l1){ l1 = acc[e]; i1 = e; }
        // softmax-topk + renorm collapses to 2-way logistic (denominators cancel)
        float q  = expf(l1 - l0);
        float w0 = 1.f / (1.f + q);
        float w1 = q  / (1.f + q);
        g_tk_idx[warp*2+0] = i0; g_tk_idx[warp*2+1] = i1;
        g_tk_w [warp*2+0] = w0; g_tk_w [warp*2+1] = w1;
    }
}

// ---------------- build per-expert token lists (64-aligned segments) ----------------
__global__ void build_kernel(){
    __shared__ int cnt[NE];
    __shared__ int offs[NE+1];
    __shared__ int cur[NE];
    int tid = threadIdx.x;
    if (tid < NE) cnt[tid] = 0;
    __syncthreads();
    for (int i = tid; i < TT*2; i += blockDim.x) atomicAdd(&cnt[g_tk_idx[i]], 1);
    __syncthreads();
    if (tid == 0){
        int o = 0;
        for (int e = 0; e < NE; e++){ offs[e] = o; cur[e] = o; o += (cnt[e] + 63) & ~63; }
        offs[NE] = o;
        for (int e = 0; e <= NE; e++) g_offs[e] = offs[e];
    }
    __syncthreads();
    for (int i = tid; i < MAX_ASSIGN; i += blockDim.x){ g_tok[i] = -1; g_twt[i] = 0.f; }
    __syncthreads();
    for (int i = tid; i < TT*2; i += blockDim.x){
        int e = g_tk_idx[i];
        int slot = atomicAdd(&cur[e], 1);
        g_tok[slot] = i >> 1;
        g_twt[slot] = g_tk_w[i];
    }
}

// ---------------- GEMM 1: gathered x @ {w_gate,w_up}^T -> act = silu(h)*u ----------------
__global__ __launch_bounds__(128) void gateup_kernel(const float* __restrict__ x,
        const float* __restrict__ wg, const float* __restrict__ wu){
    __shared__ uint32_t sA [64][SROW];
    __shared__ uint32_t sBg[64][SROW];
    __shared__ uint32_t sBu[64][SROW];
    __shared__ int sTok[64];

    int nb   = blockIdx.x * 64;   // offset into FF
    int row0 = blockIdx.y * 64;   // assignment-row tile
    int tid  = threadIdx.x;

    int e = 0;
#pragma unroll
    for (int i = 0; i < NE-1; i++) if (row0 >= g_offs[i+1]) e = i + 1;

    if (tid < 64) sTok[tid] = g_tok[row0 + tid];
    __syncthreads();

    const float* wgB = wg + (size_t)(e*FF + nb) * DD;
    const float* wuB = wu + (size_t)(e*FF + nb) * DD;

    int warp = tid >> 5, lane = tid & 31;
    int g = lane >> 2, tg = lane & 3;
    int wm = warp & 1, wn = warp >> 1;

    float hC[2][4][4], uC[2][4][4];
#pragma unroll
    for (int mi = 0; mi < 2; mi++)
#pragma unroll
        for (int ni = 0; ni < 4; ni++)
#pragma unroll
            for (int j = 0; j < 4; j++){ hC[mi][ni][j] = 0.f; uC[mi][ni][j] = 0.f; }

    for (int kc = 0; kc < DD; kc += KC){
        __syncthreads();
#pragma unroll
        for (int i = 0; i < 4; i++){
            int idx = tid + i*128;
            int r = idx >> 3;
            int c = (idx & 7) << 2;
            int tok = sTok[r];
            float4 av = make_float4(0.f,0.f,0.f,0.f);
            if (tok >= 0) av = *reinterpret_cast<const float4*>(x + (size_t)tok*DD + kc + c);
            sA[r][c+0]=f2tf(av.x); sA[r][c+1]=f2tf(av.y); sA[r][c+2]=f2tf(av.z); sA[r][c+3]=f2tf(av.w);
            float4 gv = *reinterpret_cast<const float4*>(wgB + (size_t)r*DD + kc + c);
            sBg[r][c+0]=f2tf(gv.x); sBg[r][c+1]=f2tf(gv.y); sBg[r][c+2]=f2tf(gv.z); sBg[r][c+3]=f2tf(gv.w);
            float4 uv = *reinterpret_cast<const float4*>(wuB + (size_t)r*DD + kc + c);
            sBu[r][c+0]=f2tf(uv.x); sBu[r][c+1]=f2tf(uv.y); sBu[r][c+2]=f2tf(uv.z); sBu[r][c+3]=f2tf(uv.w);
        }
        __syncthreads();
#pragma unroll
        for (int ks = 0; ks < KC; ks += 8){
            uint32_t a[2][4];
#pragma unroll
            for (int mi = 0; mi < 2; mi++){
                int r0 = wm*32 + mi*16 + g;
                a[mi][0] = sA[r0  ][ks+tg];   a[mi][1] = sA[r0+8][ks+tg];
                a[mi][2] = sA[r0  ][ks+tg+4]; a[mi][3] = sA[r0+8][ks+tg+4];
            }
#pragma unroll
            for (int ni = 0; ni < 4; ni++){
                int br = wn*32 + ni*8 + g;
                uint32_t bg0 = sBg[br][ks+tg], bg1 = sBg[br][ks+tg+4];
                uint32_t bu0 = sBu[br][ks+tg], bu1 = sBu[br][ks+tg+4];
#pragma unroll
                for (int mi = 0; mi < 2; mi++){
                    mma_tf32(hC[mi][ni], a[mi][0],a[mi][1],a[mi][2],a[mi][3], bg0, bg1);
                    mma_tf32(uC[mi][ni], a[mi][0],a[mi][1],a[mi][2],a[mi][3], bu0, bu1);
                }
            }
        }
    }
    // epilogue: act = silu(h) * u
#pragma unroll
    for (int mi = 0; mi < 2; mi++)
#pragma unroll
        for (int ni = 0; ni < 4; ni++)
#pragma unroll
            for (int half = 0; half < 2; half++){
                int r  = row0 + wm*32 + mi*16 + g + half*8;
                int cb = nb + wn*32 + ni*8 + tg*2;
                float h0 = hC[mi][ni][half*2+0], h1 = hC[mi][ni][half*2+1];
                float u0 = uC[mi][ni][half*2+0], u1 = uC[mi][ni][half*2+1];
                float v0 = h0 / (1.f + expf(-h0)) * u0;
                float v1 = h1 / (1.f + expf(-h1)) * u1;
                *reinterpret_cast<float2*>(&g_act[(size_t)r*FF + cb]) = make_float2(v0, v1);
            }
}

// ---------------- GEMM 2: act @ w_down^T, weighted scatter into out ----------------
__global__ __launch_bounds__(128) void down_kernel(const float* __restrict__ wd,
                                                   float* __restrict__ out){
    __shared__ uint32_t sA[64][SROW];
    __shared__ uint32_t sB[64][SROW];
    __shared__ int   sTok[64];
    __shared__ float sWt[64];

    int nb   = blockIdx.x * 64;   // offset into DD
    int row0 = blockIdx.y * 64;
    int tid  = threadIdx.x;

    int e = 0;
#pragma unroll
    for (int i = 0; i < NE-1; i++) if (row0 >= g_offs[i+1]) e = i + 1;

    if (tid < 64){ sTok[tid] = g_tok[row0 + tid]; sWt[tid] = g_twt[row0 + tid]; }
    __syncthreads();

    const float* wdB = wd + (size_t)(e*DD + nb) * FF;

    int warp = tid >> 5, lane = tid & 31;
    int g = lane >> 2, tg = lane & 3;
    int wm = warp & 1, wn = warp >> 1;

    float C[2][4][4];
#pragma unroll
    for (int mi = 0; mi < 2; mi++)
#pragma unroll
        for (int ni = 0; ni < 4; ni++)
#pragma unroll
            for (int j = 0; j < 4; j++) C[mi][ni][j] = 0.f;

    for (int kc = 0; kc < FF; kc += KC){
        __syncthreads();
#pragma unroll
        for (int i = 0; i < 4; i++){
            int idx = tid + i*128;
            int r = idx >> 3;
            int c = (idx & 7) << 2;
            float4 av = *reinterpret_cast<const float4*>(&g_act[(size_t)(row0+r)*FF + kc + c]);
            sA[r][c+0]=f2tf(av.x); sA[r][c+1]=f2tf(av.y); sA[r][c+2]=f2tf(av.z); sA[r][c+3]=f2tf(av.w);
            float4 bv = *reinterpret_cast<const float4*>(wdB + (size_t)r*FF + kc + c);
            sB[r][c+0]=f2tf(bv.x); sB[r][c+1]=f2tf(bv.y); sB[r][c+2]=f2tf(bv.z); sB[r][c+3]=f2tf(bv.w);
        }
        __syncthreads();
#pragma unroll
        for (int ks = 0; ks < KC; ks += 8){
            uint32_t a[2][4];
#pragma unroll
            for (int mi = 0; mi < 2; mi++){
                int r0 = wm*32 + mi*16 + g;
                a[mi][0] = sA[r0  ][ks+tg];   a[mi][1] = sA[r0+8][ks+tg];
                a[mi][2] = sA[r0  ][ks+tg+4]; a[mi][3] = sA[r0+8][ks+tg+4];
            }
#pragma unroll
            for (int ni = 0; ni < 4; ni++){
                int br = wn*32 + ni*8 + g;
                uint32_t b0 = sB[br][ks+tg], b1 = sB[br][ks+tg+4];
#pragma unroll
                for (int mi = 0; mi < 2; mi++)
                    mma_tf32(C[mi][ni], a[mi][0],a[mi][1],a[mi][2],a[mi][3], b0, b1);
            }
        }
    }
    // epilogue: out[t, :] += w * y   (exactly 2 contributions per token -> deterministic)
#pragma unroll
    for (int mi = 0; mi < 2; mi++)
#pragma unroll
        for (int half = 0; half < 2; half++){
            int rl = wm*32 + mi*16 + g + half*8;
            int t  = sTok[rl];
            if (t < 0) continue;
            float wgt = sWt[rl];
#pragma unroll
            for (int ni = 0; ni < 4; ni++){
                int cb = nb + wn*32 + ni*8 + tg*2;
                atomicAdd(&out[(size_t)t*DD + cb    ], wgt * C[mi][ni][half*2+0]);
                atomicAdd(&out[(size_t)t*DD + cb + 1], wgt * C[mi][ni][half*2+1]);
            }
        }
}

// ---------------- launch ----------------
extern "C" void kernel_launch(void* const* d_in, const int* in_sizes, int n_in,
                              void* d_out, int out_size){
    const float* x  = (const float*)d_in[0];   // [T, D]
    const float* gw = (const float*)d_in[1];   // [E, D]
    const float* wg = (const float*)d_in[2];   // [E, F, D]
    const float* wu = (const float*)d_in[3];   // [E, F, D]
    const float* wd = (const float*)d_in[4];   // [E, D, F]
    float* out    = (float*)d_out;             // [T*D] final, then [T*E] logits
    float* logits = out + (size_t)TT * DD;

    cudaMemsetAsync(out, 0, (size_t)TT * DD * sizeof(float));
    router_kernel<<<TT/8, 256>>>(x, gw, logits);
    build_kernel<<<1, 1024>>>();
    gateup_kernel<<<dim3(NT_GU, MTILES), 128>>>(x, wg, wu);
    down_kernel  <<<dim3(NT_DN, MTILES), 128>>>(wd, out);
}

// round 7
// speedup vs baseline: 1.1540x; 1.1540x over previous
#include <cuda_runtime.h>
#include <cstdint>
#include <math.h>

#define TT 8192
#define DD 2048
#define NE 8
#define FF 1408
#define KC 32              /* k-chunk */
#define SROW 36            /* padded smem row stride (words) */
#define THREADS 256
#define MAX_ASSIGN 17408   /* 136 * 128 : 16384 assignments + per-expert 128-alignment padding */
#define MT 136             /* row tiles of 128 */

// ---------------- scratch (device globals only; no allocation) ----------------
__device__ int   g_tk_idx[TT*2];
__device__ float g_tk_w[TT*2];
__device__ int   g_offs[NE+1];
__device__ int   g_tok[MAX_ASSIGN];
__device__ float g_twt[MAX_ASSIGN];
__device__ float g_act[(size_t)MAX_ASSIGN * FF];   // silu(h)*u, fp32

// ---------------- helpers ----------------
__device__ __forceinline__ uint32_t f2tf(float f){
    uint32_t u; asm("cvt.rna.tf32.f32 %0, %1;" : "=r"(u) : "f"(f)); return u;
}
__device__ __forceinline__ void mma_tf32(float c[4],
        uint32_t a0, uint32_t a1, uint32_t a2, uint32_t a3,
        uint32_t b0, uint32_t b1){
    asm volatile(
        "mma.sync.aligned.m16n8k8.row.col.f32.tf32.tf32.f32 "
        "{%0,%1,%2,%3}, {%4,%5,%6,%7}, {%8,%9}, {%0,%1,%2,%3};\n"
        : "+f"(c[0]), "+f"(c[1]), "+f"(c[2]), "+f"(c[3])
        : "r"(a0), "r"(a1), "r"(a2), "r"(a3), "r"(b0), "r"(b1));
}

// ---------------- router: logits, top-2, renormalized weights ----------------
__global__ void router_kernel(const float* __restrict__ x,
                              const float* __restrict__ gw,
                              float* __restrict__ logits){
    int warp = (blockIdx.x * blockDim.x + threadIdx.x) >> 5;
    int lane = threadIdx.x & 31;
    if (warp >= TT) return;
    const float* xr = x + (size_t)warp * DD;
    float acc[NE];
#pragma unroll
    for (int e = 0; e < NE; e++) acc[e] = 0.f;
    for (int c = lane * 4; c < DD; c += 128){
        float4 xv = *reinterpret_cast<const float4*>(xr + c);
#pragma unroll
        for (int e = 0; e < NE; e++){
            float4 gv = *reinterpret_cast<const float4*>(gw + e*DD + c);
            acc[e] += xv.x*gv.x; acc[e] += xv.y*gv.y;
            acc[e] += xv.z*gv.z; acc[e] += xv.w*gv.w;
        }
    }
#pragma unroll
    for (int e = 0; e < NE; e++){
#pragma unroll
        for (int o = 16; o > 0; o >>= 1) acc[e] += __shfl_xor_sync(0xffffffffu, acc[e], o);
    }
    if (lane == 0){
#pragma unroll
        for (int e = 0; e < NE; e++) logits[(size_t)warp*NE + e] = acc[e];
        int i0 = 0; float l0 = acc[0];
#pragma unroll
        for (int e = 1; e < NE; e++) if (acc[e] > l0){ l0 = acc[e]; i0 = e; }
        int i1 = -1; float l1 = -1e30f;
#pragma unroll
        for (int e = 0; e < NE; e++) if (e != i0 && acc[e] > l1){ l1 = acc[e]; i1 = e; }
        // softmax-topk + renorm collapses to 2-way logistic (denominators cancel)
        float q  = expf(l1 - l0);
        float w0 = 1.f / (1.f + q);
        float w1 = q  / (1.f + q);
        g_tk_idx[warp*2+0] = i0; g_tk_idx[warp*2+1] = i1;
        g_tk_w [warp*2+0] = w0; g_tk_w [warp*2+1] = w1;
    }
}

// ---------------- build per-expert token lists (128-aligned segments) ----------------
__global__ void build_kernel(){
    __shared__ int cnt[NE];
    __shared__ int offs[NE+1];
    __shared__ int cur[NE];
    int tid = threadIdx.x;
    if (tid < NE) cnt[tid] = 0;
    __syncthreads();
    for (int i = tid; i < TT*2; i += blockDim.x) atomicAdd(&cnt[g_tk_idx[i]], 1);
    __syncthreads();
    if (tid == 0){
        int o = 0;
        for (int e = 0; e < NE; e++){ offs[e] = o; cur[e] = o; o += (cnt[e] + 127) & ~127; }
        offs[NE] = o;
        for (int e = 0; e <= NE; e++) g_offs[e] = offs[e];
    }
    __syncthreads();
    for (int i = tid; i < MAX_ASSIGN; i += blockDim.x){ g_tok[i] = -1; g_twt[i] = 0.f; }
    __syncthreads();
    for (int i = tid; i < TT*2; i += blockDim.x){
        int e = g_tk_idx[i];
        int slot = atomicAdd(&cur[e], 1);
        g_tok[slot] = i >> 1;
        g_twt[slot] = g_tk_w[i];
    }
}

// ---------------- GEMM 1: gathered x @ {w_gate,w_up}^T -> act = silu(h)*u ----------------
// Block: 128 rows x 64 F-cols. 8 warps; warp tile = 32 rows x 32 F-cols, each warp
// computes BOTH h (gate) and u (up) for its patch (A fragments reused across both).
__global__ __launch_bounds__(THREADS) void gateup_kernel(const float* __restrict__ x,
        const float* __restrict__ wg, const float* __restrict__ wu){
    __shared__ uint32_t sA [128][SROW];
    __shared__ uint32_t sBg[64][SROW];
    __shared__ uint32_t sBu[64][SROW];
    __shared__ int sTok[128];

    int fb   = blockIdx.x * 64;    // F-column base
    int row0 = blockIdx.y * 128;   // assignment-row tile
    int tid  = threadIdx.x;

    if (row0 >= g_offs[NE]) return;   // fully-dead padding tile (uniform exit, pre-barrier)

    int e = 0;
#pragma unroll
    for (int i = 0; i < NE-1; i++) if (row0 >= g_offs[i+1]) e = i + 1;

    if (tid < 128) sTok[tid] = g_tok[row0 + tid];
    __syncthreads();

    const float* wgB = wg + (size_t)(e*FF + fb) * DD;
    const float* wuB = wu + (size_t)(e*FF + fb) * DD;

    int warp = tid >> 5, lane = tid & 31;
    int g = lane >> 2, tg = lane & 3;
    int wm = warp & 3, wn = warp >> 2;    // 4 m-tiles of 32 rows, 2 n-tiles of 32 F-cols

    float hC[2][4][4], uC[2][4][4];
#pragma unroll
    for (int mi = 0; mi < 2; mi++)
#pragma unroll
        for (int ni = 0; ni < 4; ni++)
#pragma unroll
            for (int j = 0; j < 4; j++){ hC[mi][ni][j] = 0.f; uC[mi][ni][j] = 0.f; }

    for (int kc = 0; kc < DD; kc += KC){
        __syncthreads();
        // A: 128 rows x 32 cols = 1024 float4, 4 per thread
#pragma unroll
        for (int i = 0; i < 4; i++){
            int idx = tid + i*256;
            int r = idx >> 3;
            int c = (idx & 7) << 2;
            int tok = sTok[r];
            float4 av = make_float4(0.f,0.f,0.f,0.f);
            if (tok >= 0) av = *reinterpret_cast<const float4*>(x + (size_t)tok*DD + kc + c);
            *reinterpret_cast<uint4*>(&sA[r][c]) =
                make_uint4(f2tf(av.x), f2tf(av.y), f2tf(av.z), f2tf(av.w));
        }
        // Bg/Bu: 64 rows x 32 cols each = 512 float4, 2 per thread each
#pragma unroll
        for (int i = 0; i < 2; i++){
            int idx = tid + i*256;
            int r = idx >> 3;
            int c = (idx & 7) << 2;
            float4 gv = *reinterpret_cast<const float4*>(wgB + (size_t)r*DD + kc + c);
            *reinterpret_cast<uint4*>(&sBg[r][c]) =
                make_uint4(f2tf(gv.x), f2tf(gv.y), f2tf(gv.z), f2tf(gv.w));
            float4 uv = *reinterpret_cast<const float4*>(wuB + (size_t)r*DD + kc + c);
            *reinterpret_cast<uint4*>(&sBu[r][c]) =
                make_uint4(f2tf(uv.x), f2tf(uv.y), f2tf(uv.z), f2tf(uv.w));
        }
        __syncthreads();
#pragma unroll
        for (int ks = 0; ks < KC; ks += 8){
            uint32_t a[2][4];
#pragma unroll
            for (int mi = 0; mi < 2; mi++){
                int r0 = wm*32 + mi*16 + g;
                a[mi][0] = sA[r0  ][ks+tg];   a[mi][1] = sA[r0+8][ks+tg];
                a[mi][2] = sA[r0  ][ks+tg+4]; a[mi][3] = sA[r0+8][ks+tg+4];
            }
#pragma unroll
            for (int ni = 0; ni < 4; ni++){
                int br = wn*32 + ni*8 + g;
                uint32_t bg0 = sBg[br][ks+tg], bg1 = sBg[br][ks+tg+4];
                uint32_t bu0 = sBu[br][ks+tg], bu1 = sBu[br][ks+tg+4];
#pragma unroll
                for (int mi = 0; mi < 2; mi++){
                    mma_tf32(hC[mi][ni], a[mi][0],a[mi][1],a[mi][2],a[mi][3], bg0, bg1);
                    mma_tf32(uC[mi][ni], a[mi][0],a[mi][1],a[mi][2],a[mi][3], bu0, bu1);
                }
            }
        }
    }
    // epilogue: act = silu(h) * u
#pragma unroll
    for (int mi = 0; mi < 2; mi++)
#pragma unroll
        for (int ni = 0; ni < 4; ni++)
#pragma unroll
            for (int half = 0; half < 2; half++){
                int r    = row0 + wm*32 + mi*16 + g + half*8;
                int fcol = fb + wn*32 + ni*8 + tg*2;
                float h0 = hC[mi][ni][half*2+0], h1 = hC[mi][ni][half*2+1];
                float u0 = uC[mi][ni][half*2+0], u1 = uC[mi][ni][half*2+1];
                float v0 = h0 / (1.f + expf(-h0)) * u0;
                float v1 = h1 / (1.f + expf(-h1)) * u1;
                *reinterpret_cast<float2*>(&g_act[(size_t)r*FF + fcol]) = make_float2(v0, v1);
            }
}

// ---------------- GEMM 2: act @ w_down^T, weighted scatter into out ----------------
// Block: 128 rows x 128 D-cols. 8 warps; warp tile = 64 rows x 32 cols.
__global__ __launch_bounds__(THREADS) void down_kernel(const float* __restrict__ wd,
                                                       float* __restrict__ out){
    __shared__ uint32_t sA[128][SROW];
    __shared__ uint32_t sB[128][SROW];
    __shared__ int   sTok[128];
    __shared__ float sWt[128];

    int nb   = blockIdx.x * 128;   // D-column base
    int row0 = blockIdx.y * 128;
    int tid  = threadIdx.x;

    if (row0 >= g_offs[NE]) return;   // fully-dead padding tile

    int e = 0;
#pragma unroll
    for (int i = 0; i < NE-1; i++) if (row0 >= g_offs[i+1]) e = i + 1;

    if (tid < 128){ sTok[tid] = g_tok[row0 + tid]; sWt[tid] = g_twt[row0 + tid]; }
    __syncthreads();

    const float* wdB = wd + (size_t)(e*DD + nb) * FF;

    int warp = tid >> 5, lane = tid & 31;
    int g = lane >> 2, tg = lane & 3;
    int wm = warp & 1, wn = warp >> 1;   // 2 m-tiles of 64 rows, 4 n-tiles of 32 cols

    float C[4][4][4];
#pragma unroll
    for (int mi = 0; mi < 4; mi++)
#pragma unroll
        for (int ni = 0; ni < 4; ni++)
#pragma unroll
            for (int j = 0; j < 4; j++) C[mi][ni][j] = 0.f;

    for (int kc = 0; kc < FF; kc += KC){
        __syncthreads();
        // A and B: 128 rows x 32 cols each = 1024 float4, 4 per thread each
#pragma unroll
        for (int i = 0; i < 4; i++){
            int idx = tid + i*256;
            int r = idx >> 3;
            int c = (idx & 7) << 2;
            float4 av = *reinterpret_cast<const float4*>(&g_act[(size_t)(row0+r)*FF + kc + c]);
            *reinterpret_cast<uint4*>(&sA[r][c]) =
                make_uint4(f2tf(av.x), f2tf(av.y), f2tf(av.z), f2tf(av.w));
            float4 bv = *reinterpret_cast<const float4*>(wdB + (size_t)r*FF + kc + c);
            *reinterpret_cast<uint4*>(&sB[r][c]) =
                make_uint4(f2tf(bv.x), f2tf(bv.y), f2tf(bv.z), f2tf(bv.w));
        }
        __syncthreads();
#pragma unroll
        for (int ks = 0; ks < KC; ks += 8){
            uint32_t a[4][4], b[4][2];
#pragma unroll
            for (int mi = 0; mi < 4; mi++){
                int r0 = wm*64 + mi*16 + g;
                a[mi][0] = sA[r0  ][ks+tg];   a[mi][1] = sA[r0+8][ks+tg];
                a[mi][2] = sA[r0  ][ks+tg+4]; a[mi][3] = sA[r0+8][ks+tg+4];
            }
#pragma unroll
            for (int ni = 0; ni < 4; ni++){
                int br = wn*32 + ni*8 + g;
                b[ni][0] = sB[br][ks+tg]; b[ni][1] = sB[br][ks+tg+4];
            }
#pragma unroll
            for (int mi = 0; mi < 4; mi++)
#pragma unroll
                for (int ni = 0; ni < 4; ni++)
                    mma_tf32(C[mi][ni], a[mi][0],a[mi][1],a[mi][2],a[mi][3], b[ni][0], b[ni][1]);
        }
    }
    // epilogue: out[t, :] += w * y   (exactly 2 contributions per token -> deterministic)
#pragma unroll
    for (int mi = 0; mi < 4; mi++)
#pragma unroll
        for (int half = 0; half < 2; half++){
            int rl = wm*64 + mi*16 + g + half*8;
            int t  = sTok[rl];
            if (t < 0) continue;
            float wgt = sWt[rl];
#pragma unroll
            for (int ni = 0; ni < 4; ni++){
                int cb = nb + wn*32 + ni*8 + tg*2;
                atomicAdd(&out[(size_t)t*DD + cb    ], wgt * C[mi][ni][half*2+0]);
                atomicAdd(&out[(size_t)t*DD + cb + 1], wgt * C[mi][ni][half*2+1]);
            }
        }
}

// ---------------- launch ----------------
extern "C" void kernel_launch(void* const* d_in, const int* in_sizes, int n_in,
                              void* d_out, int out_size){
    const float* x  = (const float*)d_in[0];   // [T, D]
    const float* gw = (const float*)d_in[1];   // [E, D]
    const float* wg = (const float*)d_in[2];   // [E, F, D]
    const float* wu = (const float*)d_in[3];   // [E, F, D]
    const float* wd = (const float*)d_in[4];   // [E, D, F]
    float* out    = (float*)d_out;             // [T*D] final, then [T*E] logits
    float* logits = out + (size_t)TT * DD;

    cudaMemsetAsync(out, 0, (size_t)TT * DD * sizeof(float));
    router_kernel<<<TT/8, 256>>>(x, gw, logits);
    build_kernel<<<1, 1024>>>();
    gateup_kernel<<<dim3(FF/64, MT), THREADS>>>(x, wg, wu);
    down_kernel  <<<dim3(DD/128, MT), THREADS>>>(wd, out);
}

// round 8
// speedup vs baseline: 1.3919x; 1.2061x over previous
#include <cuda_runtime.h>
#include <cstdint>
#include <math.h>

#define TT 8192
#define DD 2048
#define NE 8
#define FF 1408
#define KC 16              /* k-chunk */
#define SROW 20            /* padded smem row stride (words) = KC + 4 */
#define THREADS 256
#define MAX_ASSIGN 17408   /* 136 * 128 : 16384 assignments + per-expert 128-alignment padding */
#define MT 136             /* row tiles of 128 */

// ---------------- scratch (device globals only; no allocation) ----------------
__device__ int   g_tk_idx[TT*2];
__device__ float g_tk_w[TT*2];
__device__ int   g_offs[NE+1];
__device__ int   g_tok[MAX_ASSIGN];
__device__ float g_twt[MAX_ASSIGN];
__device__ float g_act[(size_t)MAX_ASSIGN * FF];   // silu(h)*u, fp32

// ---------------- helpers ----------------
__device__ __forceinline__ uint32_t f2tf(float f){
    uint32_t u; asm("cvt.rna.tf32.f32 %0, %1;" : "=r"(u) : "f"(f)); return u;
}
__device__ __forceinline__ void mma_tf32(float c[4],
        uint32_t a0, uint32_t a1, uint32_t a2, uint32_t a3,
        uint32_t b0, uint32_t b1){
    asm volatile(
        "mma.sync.aligned.m16n8k8.row.col.f32.tf32.tf32.f32 "
        "{%0,%1,%2,%3}, {%4,%5,%6,%7}, {%8,%9}, {%0,%1,%2,%3};\n"
        : "+f"(c[0]), "+f"(c[1]), "+f"(c[2]), "+f"(c[3])
        : "r"(a0), "r"(a1), "r"(a2), "r"(a3), "r"(b0), "r"(b1));
}
__device__ __forceinline__ void sts_tf4(uint32_t* dst, float4 v){
    *reinterpret_cast<uint4*>(dst) = make_uint4(f2tf(v.x), f2tf(v.y), f2tf(v.z), f2tf(v.w));
}

// ---------------- router: logits, top-2, renormalized weights ----------------
__global__ void router_kernel(const float* __restrict__ x,
                              const float* __restrict__ gw,
                              float* __restrict__ logits){
    int warp = (blockIdx.x * blockDim.x + threadIdx.x) >> 5;
    int lane = threadIdx.x & 31;
    if (warp >= TT) return;
    const float* xr = x + (size_t)warp * DD;
    float acc[NE];
#pragma unroll
    for (int e = 0; e < NE; e++) acc[e] = 0.f;
    for (int c = lane * 4; c < DD; c += 128){
        float4 xv = *reinterpret_cast<const float4*>(xr + c);
#pragma unroll
        for (int e = 0; e < NE; e++){
            float4 gv = *reinterpret_cast<const float4*>(gw + e*DD + c);
            acc[e] += xv.x*gv.x; acc[e] += xv.y*gv.y;
            acc[e] += xv.z*gv.z; acc[e] += xv.w*gv.w;
        }
    }
#pragma unroll
    for (int e = 0; e < NE; e++){
#pragma unroll
        for (int o = 16; o > 0; o >>= 1) acc[e] += __shfl_xor_sync(0xffffffffu, acc[e], o);
    }
    if (lane == 0){
#pragma unroll
        for (int e = 0; e < NE; e++) logits[(size_t)warp*NE + e] = acc[e];
        int i0 = 0; float l0 = acc[0];
#pragma unroll
        for (int e = 1; e < NE; e++) if (acc[e] > l0){ l0 = acc[e]; i0 = e; }
        int i1 = -1; float l1 = -1e30f;
#pragma unroll
        for (int e = 0; e < NE; e++) if (e != i0 && acc[e] > l1){ l1 = acc[e]; i1 = e; }
        // softmax-topk + renorm collapses to 2-way logistic (denominators cancel)
        float q  = expf(l1 - l0);
        float w0 = 1.f / (1.f + q);
        float w1 = q  / (1.f + q);
        g_tk_idx[warp*2+0] = i0; g_tk_idx[warp*2+1] = i1;
        g_tk_w [warp*2+0] = w0; g_tk_w [warp*2+1] = w1;
    }
}

// ---------------- build per-expert token lists (128-aligned segments) ----------------
__global__ void build_kernel(){
    __shared__ int cnt[NE];
    __shared__ int offs[NE+1];
    __shared__ int cur[NE];
    int tid = threadIdx.x;
    if (tid < NE) cnt[tid] = 0;
    __syncthreads();
    for (int i = tid; i < TT*2; i += blockDim.x) atomicAdd(&cnt[g_tk_idx[i]], 1);
    __syncthreads();
    if (tid == 0){
        int o = 0;
        for (int e = 0; e < NE; e++){ offs[e] = o; cur[e] = o; o += (cnt[e] + 127) & ~127; }
        offs[NE] = o;
        for (int e = 0; e <= NE; e++) g_offs[e] = offs[e];
    }
    __syncthreads();
    for (int i = tid; i < MAX_ASSIGN; i += blockDim.x){ g_tok[i] = -1; g_twt[i] = 0.f; }
    __syncthreads();
    for (int i = tid; i < TT*2; i += blockDim.x){
        int e = g_tk_idx[i];
        int slot = atomicAdd(&cur[e], 1);
        g_tok[slot] = i >> 1;
        g_twt[slot] = g_tk_w[i];
    }
}

// ---------------- GEMM 1: gathered x @ {w_gate,w_up}^T -> act = silu(h)*u ----------------
// Block: 128 rows x 64 F-cols, double-buffered smem, one barrier per k-chunk.
// 8 warps; warp tile = 32 rows x 32 F-cols, each warp computes BOTH h and u.
__global__ __launch_bounds__(THREADS, 2) void gateup_kernel(const float* __restrict__ x,
        const float* __restrict__ wg, const float* __restrict__ wu){
    __shared__ uint32_t sA [2][128][SROW];
    __shared__ uint32_t sBg[2][64][SROW];
    __shared__ uint32_t sBu[2][64][SROW];
    __shared__ int sTok[128];

    int fb   = blockIdx.x * 64;    // F-column base
    int row0 = blockIdx.y * 128;   // assignment-row tile
    int tid  = threadIdx.x;

    if (row0 >= g_offs[NE]) return;   // fully-dead padding tile (uniform exit, pre-barrier)

    int e = 0;
#pragma unroll
    for (int i = 0; i < NE-1; i++) if (row0 >= g_offs[i+1]) e = i + 1;

    if (tid < 128) sTok[tid] = g_tok[row0 + tid];
    __syncthreads();

    int warp = tid >> 5, lane = tid & 31;
    int g = lane >> 2, tg = lane & 3;
    int wm = warp & 3, wn = warp >> 2;    // 4 m-tiles of 32 rows, 2 n-tiles of 32 F-cols

    // loader mapping: 4 threads per row, KC=16 words per row
    int rL = tid >> 2;            // 0..63
    int c0 = (tid & 3) << 2;      // 0,4,8,12

    const float* aP[2];
#pragma unroll
    for (int i = 0; i < 2; i++){
        int tok = sTok[rL + 64*i];
        aP[i] = (tok >= 0) ? (x + (size_t)tok * DD + c0) : (const float*)0;
    }
    const float* gP = wg + (size_t)(e*FF + fb + rL) * DD + c0;
    const float* uP = wu + (size_t)(e*FF + fb + rL) * DD + c0;

    float hC[2][4][4], uC[2][4][4];
#pragma unroll
    for (int mi = 0; mi < 2; mi++)
#pragma unroll
        for (int ni = 0; ni < 4; ni++)
#pragma unroll
            for (int j = 0; j < 4; j++){ hC[mi][ni][j] = 0.f; uC[mi][ni][j] = 0.f; }

    float4 aS[2], gS, uS;
#pragma unroll
    for (int i = 0; i < 2; i++)
        aS[i] = aP[i] ? *reinterpret_cast<const float4*>(aP[i]) : make_float4(0.f,0.f,0.f,0.f);
    gS = *reinterpret_cast<const float4*>(gP);
    uS = *reinterpret_cast<const float4*>(uP);
#pragma unroll
    for (int i = 0; i < 2; i++) sts_tf4(&sA[0][rL + 64*i][c0], aS[i]);
    sts_tf4(&sBg[0][rL][c0], gS);
    sts_tf4(&sBu[0][rL][c0], uS);
    __syncthreads();

    const int NCH = DD / KC;
    for (int ck = 0; ck < NCH; ck++){
        int cur = ck & 1;
        bool more = (ck + 1) < NCH;
        int koff = (ck + 1) * KC;
        if (more){
#pragma unroll
            for (int i = 0; i < 2; i++)
                aS[i] = aP[i] ? *reinterpret_cast<const float4*>(aP[i] + koff)
                              : make_float4(0.f,0.f,0.f,0.f);
            gS = *reinterpret_cast<const float4*>(gP + koff);
            uS = *reinterpret_cast<const float4*>(uP + koff);
        }
#pragma unroll
        for (int ks = 0; ks < KC; ks += 8){
            uint32_t a[2][4];
#pragma unroll
            for (int mi = 0; mi < 2; mi++){
                int r0 = wm*32 + mi*16 + g;
                a[mi][0] = sA[cur][r0  ][ks+tg];   a[mi][1] = sA[cur][r0+8][ks+tg];
                a[mi][2] = sA[cur][r0  ][ks+tg+4]; a[mi][3] = sA[cur][r0+8][ks+tg+4];
            }
#pragma unroll
            for (int ni = 0; ni < 4; ni++){
                int br = wn*32 + ni*8 + g;
                uint32_t bg0 = sBg[cur][br][ks+tg], bg1 = sBg[cur][br][ks+tg+4];
                uint32_t bu0 = sBu[cur][br][ks+tg], bu1 = sBu[cur][br][ks+tg+4];
#pragma unroll
                for (int mi = 0; mi < 2; mi++){
                    mma_tf32(hC[mi][ni], a[mi][0],a[mi][1],a[mi][2],a[mi][3], bg0, bg1);
                    mma_tf32(uC[mi][ni], a[mi][0],a[mi][1],a[mi][2],a[mi][3], bu0, bu1);
                }
            }
        }
        if (more){
            int nxt = cur ^ 1;
#pragma unroll
            for (int i = 0; i < 2; i++) sts_tf4(&sA[nxt][rL + 64*i][c0], aS[i]);
            sts_tf4(&sBg[nxt][rL][c0], gS);
            sts_tf4(&sBu[nxt][rL][c0], uS);
            __syncthreads();
        }
    }
    // epilogue: act = silu(h) * u
#pragma unroll
    for (int mi = 0; mi < 2; mi++)
#pragma unroll
        for (int ni = 0; ni < 4; ni++)
#pragma unroll
            for (int half = 0; half < 2; half++){
                int r    = row0 + wm*32 + mi*16 + g + half*8;
                int fcol = fb + wn*32 + ni*8 + tg*2;
                float h0 = hC[mi][ni][half*2+0], h1 = hC[mi][ni][half*2+1];
                float u0 = uC[mi][ni][half*2+0], u1 = uC[mi][ni][half*2+1];
                float v0 = h0 / (1.f + expf(-h0)) * u0;
                float v1 = h1 / (1.f + expf(-h1)) * u1;
                *reinterpret_cast<float2*>(&g_act[(size_t)r*FF + fcol]) = make_float2(v0, v1);
            }
}

// ---------------- GEMM 2: act @ w_down^T, weighted scatter into out ----------------
// Block: 128 rows x 128 D-cols, double-buffered smem, one barrier per k-chunk.
// 8 warps; warp tile = 64 rows x 32 cols.
__global__ __launch_bounds__(THREADS, 2) void down_kernel(const float* __restrict__ wd,
                                                          float* __restrict__ out){
    __shared__ uint32_t sA[2][128][SROW];
    __shared__ uint32_t sB[2][128][SROW];
    __shared__ int   sTok[128];
    __shared__ float sWt[128];

    int nb   = blockIdx.x * 128;   // D-column base
    int row0 = blockIdx.y * 128;
    int tid  = threadIdx.x;

    if (row0 >= g_offs[NE]) return;   // fully-dead padding tile

    int e = 0;
#pragma unroll
    for (int i = 0; i < NE-1; i++) if (row0 >= g_offs[i+1]) e = i + 1;

    if (tid < 128){ sTok[tid] = g_tok[row0 + tid]; sWt[tid] = g_twt[row0 + tid]; }
    __syncthreads();

    int warp = tid >> 5, lane = tid & 31;
    int g = lane >> 2, tg = lane & 3;
    int wm = warp & 1, wn = warp >> 1;   // 2 m-tiles of 64 rows, 4 n-tiles of 32 cols

    int rL = tid >> 2;            // 0..63
    int c0 = (tid & 3) << 2;      // 0,4,8,12

    const float* aP[2];
    const float* bP[2];
#pragma unroll
    for (int i = 0; i < 2; i++){
        aP[i] = g_act + (size_t)(row0 + rL + 64*i) * FF + c0;
        bP[i] = wd + (size_t)(e*DD + nb + rL + 64*i) * FF + c0;
    }

    float C[4][4][4];
#pragma unroll
    for (int mi = 0; mi < 4; mi++)
#pragma unroll
        for (int ni = 0; ni < 4; ni++)
#pragma unroll
            for (int j = 0; j < 4; j++) C[mi][ni][j] = 0.f;

    float4 aS[2], bS[2];
#pragma unroll
    for (int i = 0; i < 2; i++){
        aS[i] = *reinterpret_cast<const float4*>(aP[i]);
        bS[i] = *reinterpret_cast<const float4*>(bP[i]);
    }
#pragma unroll
    for (int i = 0; i < 2; i++){
        sts_tf4(&sA[0][rL + 64*i][c0], aS[i]);
        sts_tf4(&sB[0][rL + 64*i][c0], bS[i]);
    }
    __syncthreads();

    const int NCH = FF / KC;
    for (int ck = 0; ck < NCH; ck++){
        int cur = ck & 1;
        bool more = (ck + 1) < NCH;
        int koff = (ck + 1) * KC;
        if (more){
#pragma unroll
            for (int i = 0; i < 2; i++){
                aS[i] = *reinterpret_cast<const float4*>(aP[i] + koff);
                bS[i] = *reinterpret_cast<const float4*>(bP[i] + koff);
            }
        }
#pragma unroll
        for (int ks = 0; ks < KC; ks += 8){
            uint32_t a[4][4], b[4][2];
#pragma unroll
            for (int mi = 0; mi < 4; mi++){
                int r0 = wm*64 + mi*16 + g;
                a[mi][0] = sA[cur][r0  ][ks+tg];   a[mi][1] = sA[cur][r0+8][ks+tg];
                a[mi][2] = sA[cur][r0  ][ks+tg+4]; a[mi][3] = sA[cur][r0+8][ks+tg+4];
            }
#pragma unroll
            for (int ni = 0; ni < 4; ni++){
                int br = wn*32 + ni*8 + g;
                b[ni][0] = sB[cur][br][ks+tg]; b[ni][1] = sB[cur][br][ks+tg+4];
            }
#pragma unroll
            for (int mi = 0; mi < 4; mi++)
#pragma unroll
                for (int ni = 0; ni < 4; ni++)
                    mma_tf32(C[mi][ni], a[mi][0],a[mi][1],a[mi][2],a[mi][3], b[ni][0], b[ni][1]);
        }
        if (more){
            int nxt = cur ^ 1;
#pragma unroll
            for (int i = 0; i < 2; i++){
                sts_tf4(&sA[nxt][rL + 64*i][c0], aS[i]);
                sts_tf4(&sB[nxt][rL + 64*i][c0], bS[i]);
            }
            __syncthreads();
        }
    }
    // epilogue: out[t, :] += w * y   (exactly 2 contributions per token -> deterministic)
#pragma unroll
    for (int mi = 0; mi < 4; mi++)
#pragma unroll
        for (int half = 0; half < 2; half++){
            int rl = wm*64 + mi*16 + g + half*8;
            int t  = sTok[rl];
            if (t < 0) continue;
            float wgt = sWt[rl];
#pragma unroll
            for (int ni = 0; ni < 4; ni++){
                int cb = nb + wn*32 + ni*8 + tg*2;
                atomicAdd(&out[(size_t)t*DD + cb    ], wgt * C[mi][ni][half*2+0]);
                atomicAdd(&out[(size_t)t*DD + cb + 1], wgt * C[mi][ni][half*2+1]);
            }
        }
}

// ---------------- launch ----------------
extern "C" void kernel_launch(void* const* d_in, const int* in_sizes, int n_in,
                              void* d_out, int out_size){
    const float* x  = (const float*)d_in[0];   // [T, D]
    const float* gw = (const float*)d_in[1];   // [E, D]
    const float* wg = (const float*)d_in[2];   // [E, F, D]
    const float* wu = (const float*)d_in[3];   // [E, F, D]
    const float* wd = (const float*)d_in[4];   // [E, D, F]
    float* out    = (float*)d_out;             // [T*D] final, then [T*E] logits
    float* logits = out + (size_t)TT * DD;

    cudaMemsetAsync(out, 0, (size_t)TT * DD * sizeof(float));
    router_kernel<<<TT/8, 256>>>(x, gw, logits);
    build_kernel<<<1, 1024>>>();
    gateup_kernel<<<dim3(FF/64, MT), THREADS>>>(x, wg, wu);
    down_kernel  <<<dim3(DD/128, MT), THREADS>>>(wd, out);
}

// round 9
// speedup vs baseline: 1.5509x; 1.1142x over previous
#include <cuda_runtime.h>
#include <cstdint>
#include <math.h>

#define TT 8192
#define DD 2048
#define NE 8
#define FF 1408
#define KC 16              /* k-chunk */
#define SROW 20            /* padded smem row stride (words) = KC + 4 */
#define THREADS 128
#define MAX_ASSIGN 17408   /* 136 * 128 */
#define MT 136             /* row tiles of 128 */

// ---------------- scratch (device globals only; no allocation) ----------------
__device__ int   g_tk_idx[TT*2];
__device__ float g_tk_w[TT*2];
__device__ int   g_offs[NE+1];
__device__ int   g_tok[MAX_ASSIGN];
__device__ float g_twt[MAX_ASSIGN];
__device__ float g_act[(size_t)MAX_ASSIGN * FF];   // silu(h)*u, fp32

// ---------------- helpers ----------------
__device__ __forceinline__ uint32_t f2tf(float f){
    uint32_t u; asm("cvt.rna.tf32.f32 %0, %1;" : "=r"(u) : "f"(f)); return u;
}
__device__ __forceinline__ void mma_tf32(float c[4],
        uint32_t a0, uint32_t a1, uint32_t a2, uint32_t a3,
        uint32_t b0, uint32_t b1){
    asm volatile(
        "mma.sync.aligned.m16n8k8.row.col.f32.tf32.tf32.f32 "
        "{%0,%1,%2,%3}, {%4,%5,%6,%7}, {%8,%9}, {%0,%1,%2,%3};\n"
        : "+f"(c[0]), "+f"(c[1]), "+f"(c[2]), "+f"(c[3])
        : "r"(a0), "r"(a1), "r"(a2), "r"(a3), "r"(b0), "r"(b1));
}
__device__ __forceinline__ void sts_tf4(uint32_t* dst, float4 v){
    *reinterpret_cast<uint4*>(dst) = make_uint4(f2tf(v.x), f2tf(v.y), f2tf(v.z), f2tf(v.w));
}

// ---------------- router: logits, top-2, renormalized weights ----------------
__global__ void router_kernel(const float* __restrict__ x,
                              const float* __restrict__ gw,
                              float* __restrict__ logits){
    int warp = (blockIdx.x * blockDim.x + threadIdx.x) >> 5;
    int lane = threadIdx.x & 31;
    if (warp >= TT) return;
    const float* xr = x + (size_t)warp * DD;
    float acc[NE];
#pragma unroll
    for (int e = 0; e < NE; e++) acc[e] = 0.f;
    for (int c = lane * 4; c < DD; c += 128){
        float4 xv = *reinterpret_cast<const float4*>(xr + c);
#pragma unroll
        for (int e = 0; e < NE; e++){
            float4 gv = *reinterpret_cast<const float4*>(gw + e*DD + c);
            acc[e] += xv.x*gv.x; acc[e] += xv.y*gv.y;
            acc[e] += xv.z*gv.z; acc[e] += xv.w*gv.w;
        }
    }
#pragma unroll
    for (int e = 0; e < NE; e++){
#pragma unroll
        for (int o = 16; o > 0; o >>= 1) acc[e] += __shfl_xor_sync(0xffffffffu, acc[e], o);
    }
    if (lane == 0){
#pragma unroll
        for (int e = 0; e < NE; e++) logits[(size_t)warp*NE + e] = acc[e];
        int i0 = 0; float l0 = acc[0];
#pragma unroll
        for (int e = 1; e < NE; e++) if (acc[e] > l0){ l0 = acc[e]; i0 = e; }
        int i1 = -1; float l1 = -1e30f;
#pragma unroll
        for (int e = 0; e < NE; e++) if (e != i0 && acc[e] > l1){ l1 = acc[e]; i1 = e; }
        float q  = expf(l1 - l0);
        float w0 = 1.f / (1.f + q);
        float w1 = q  / (1.f + q);
        g_tk_idx[warp*2+0] = i0; g_tk_idx[warp*2+1] = i1;
        g_tk_w [warp*2+0] = w0; g_tk_w [warp*2+1] = w1;
    }
}

// ---------------- build per-expert token lists (128-aligned segments) ----------------
__global__ void build_kernel(){
    __shared__ int cnt[NE];
    __shared__ int offs[NE+1];
    __shared__ int cur[NE];
    int tid = threadIdx.x;
    if (tid < NE) cnt[tid] = 0;
    __syncthreads();
    for (int i = tid; i < TT*2; i += blockDim.x) atomicAdd(&cnt[g_tk_idx[i]], 1);
    __syncthreads();
    if (tid == 0){
        int o = 0;
        for (int e = 0; e < NE; e++){ offs[e] = o; cur[e] = o; o += (cnt[e] + 127) & ~127; }
        offs[NE] = o;
        for (int e = 0; e <= NE; e++) g_offs[e] = offs[e];
    }
    __syncthreads();
    for (int i = tid; i < MAX_ASSIGN; i += blockDim.x){ g_tok[i] = -1; g_twt[i] = 0.f; }
    __syncthreads();
    for (int i = tid; i < TT*2; i += blockDim.x){
        int e = g_tk_idx[i];
        int slot = atomicAdd(&cur[e], 1);
        g_tok[slot] = i >> 1;
        g_twt[slot] = g_tk_w[i];
    }
}

// ---------------- GEMM 1: gathered x @ {w_gate,w_up}^T -> act = silu(h)*u ----------------
// Block: 128 rows x 64 F-cols; 4 warps; warp tile = 64 rows x 32 F-cols x BOTH h,u.
// Double-buffered smem, register-staged prefetch, one barrier per k-chunk.
__global__ __launch_bounds__(THREADS) void gateup_kernel(const float* __restrict__ x,
        const float* __restrict__ wg, const float* __restrict__ wu){
    __shared__ uint32_t sA [2][128][SROW];
    __shared__ uint32_t sBg[2][64][SROW];
    __shared__ uint32_t sBu[2][64][SROW];
    __shared__ int sTok[128];

    int fb   = blockIdx.x * 64;    // F-column base
    int row0 = blockIdx.y * 128;   // assignment-row tile
    int tid  = threadIdx.x;

    if (row0 >= g_offs[NE]) return;   // fully-dead padding tile

    int e = 0;
#pragma unroll
    for (int i = 0; i < NE-1; i++) if (row0 >= g_offs[i+1]) e = i + 1;

    sTok[tid] = g_tok[row0 + tid];
    __syncthreads();

    int warp = tid >> 5, lane = tid & 31;
    int g = lane >> 2, tg = lane & 3;
    int wm = warp & 1, wn = warp >> 1;    // 2 m-tiles of 64 rows, 2 n-tiles of 32 F-cols

    // loader mapping: 4 threads per row, KC=16 words per row
    int rL = tid >> 2;            // 0..31
    int c0 = (tid & 3) << 2;      // 0,4,8,12

    const float* aP[4];
#pragma unroll
    for (int i = 0; i < 4; i++){
        int tok = sTok[rL + 32*i];
        aP[i] = (tok >= 0) ? (x + (size_t)tok * DD + c0) : (const float*)0;
    }
    const float* gP[2];
    const float* uP[2];
#pragma unroll
    for (int i = 0; i < 2; i++){
        gP[i] = wg + (size_t)(e*FF + fb + rL + 32*i) * DD + c0;
        uP[i] = wu + (size_t)(e*FF + fb + rL + 32*i) * DD + c0;
    }

    float hC[4][4][4], uC[4][4][4];
#pragma unroll
    for (int mi = 0; mi < 4; mi++)
#pragma unroll
        for (int ni = 0; ni < 4; ni++)
#pragma unroll
            for (int j = 0; j < 4; j++){ hC[mi][ni][j] = 0.f; uC[mi][ni][j] = 0.f; }

    float4 aS[4], gS[2], uS[2];
#pragma unroll
    for (int i = 0; i < 4; i++)
        aS[i] = aP[i] ? *reinterpret_cast<const float4*>(aP[i]) : make_float4(0.f,0.f,0.f,0.f);
#pragma unroll
    for (int i = 0; i < 2; i++){
        gS[i] = *reinterpret_cast<const float4*>(gP[i]);
        uS[i] = *reinterpret_cast<const float4*>(uP[i]);
    }
#pragma unroll
    for (int i = 0; i < 4; i++) sts_tf4(&sA[0][rL + 32*i][c0], aS[i]);
#pragma unroll
    for (int i = 0; i < 2; i++){
        sts_tf4(&sBg[0][rL + 32*i][c0], gS[i]);
        sts_tf4(&sBu[0][rL + 32*i][c0], uS[i]);
    }
    __syncthreads();

    const int NCH = DD / KC;
    for (int ck = 0; ck < NCH; ck++){
        int cur = ck & 1;
        bool more = (ck + 1) < NCH;
        int koff = (ck + 1) * KC;
        if (more){
#pragma unroll
            for (int i = 0; i < 4; i++)
                aS[i] = aP[i] ? *reinterpret_cast<const float4*>(aP[i] + koff)
                              : make_float4(0.f,0.f,0.f,0.f);
#pragma unroll
            for (int i = 0; i < 2; i++){
                gS[i] = *reinterpret_cast<const float4*>(gP[i] + koff);
                uS[i] = *reinterpret_cast<const float4*>(uP[i] + koff);
            }
        }
#pragma unroll
        for (int ks = 0; ks < KC; ks += 8){
            uint32_t a[4][4];
#pragma unroll
            for (int mi = 0; mi < 4; mi++){
                int r0 = wm*64 + mi*16 + g;
                a[mi][0] = sA[cur][r0  ][ks+tg];   a[mi][1] = sA[cur][r0+8][ks+tg];
                a[mi][2] = sA[cur][r0  ][ks+tg+4]; a[mi][3] = sA[cur][r0+8][ks+tg+4];
            }
#pragma unroll
            for (int ni = 0; ni < 4; ni++){
                int br = wn*32 + ni*8 + g;
                uint32_t bg0 = sBg[cur][br][ks+tg], bg1 = sBg[cur][br][ks+tg+4];
                uint32_t bu0 = sBu[cur][br][ks+tg], bu1 = sBu[cur][br][ks+tg+4];
#pragma unroll
                for (int mi = 0; mi < 4; mi++){
                    mma_tf32(hC[mi][ni], a[mi][0],a[mi][1],a[mi][2],a[mi][3], bg0, bg1);
                    mma_tf32(uC[mi][ni], a[mi][0],a[mi][1],a[mi][2],a[mi][3], bu0, bu1);
                }
            }
        }
        if (more){
            int nxt = cur ^ 1;
#pragma unroll
            for (int i = 0; i < 4; i++) sts_tf4(&sA[nxt][rL + 32*i][c0], aS[i]);
#pragma unroll
            for (int i = 0; i < 2; i++){
                sts_tf4(&sBg[nxt][rL + 32*i][c0], gS[i]);
                sts_tf4(&sBu[nxt][rL + 32*i][c0], uS[i]);
            }
            __syncthreads();
        }
    }
    // epilogue: act = silu(h) * u
#pragma unroll
    for (int mi = 0; mi < 4; mi++)
#pragma unroll
        for (int ni = 0; ni < 4; ni++)
#pragma unroll
            for (int half = 0; half < 2; half++){
                int r    = row0 + wm*64 + mi*16 + g + half*8;
                int fcol = fb + wn*32 + ni*8 + tg*2;
                float h0 = hC[mi][ni][half*2+0], h1 = hC[mi][ni][half*2+1];
                float u0 = uC[mi][ni][half*2+0], u1 = uC[mi][ni][half*2+1];
                float v0 = h0 / (1.f + expf(-h0)) * u0;
                float v1 = h1 / (1.f + expf(-h1)) * u1;
                *reinterpret_cast<float2*>(&g_act[(size_t)r*FF + fcol]) = make_float2(v0, v1);
            }
}

// ---------------- GEMM 2: act @ w_down^T, weighted scatter into out ----------------
// Block: 128 rows x 128 D-cols; 4 warps; warp tile = 64 rows x 64 cols.
__global__ __launch_bounds__(THREADS) void down_kernel(const float* __restrict__ wd,
                                                       float* __restrict__ out){
    __shared__ uint32_t sA[2][128][SROW];
    __shared__ uint32_t sB[2][128][SROW];
    __shared__ int   sTok[128];
    __shared__ float sWt[128];

    int nb   = blockIdx.x * 128;   // D-column base
    int row0 = blockIdx.y * 128;
    int tid  = threadIdx.x;

    if (row0 >= g_offs[NE]) return;   // fully-dead padding tile

    int e = 0;
#pragma unroll
    for (int i = 0; i < NE-1; i++) if (row0 >= g_offs[i+1]) e = i + 1;

    sTok[tid] = g_tok[row0 + tid];
    sWt[tid]  = g_twt[row0 + tid];
    __syncthreads();

    int warp = tid >> 5, lane = tid & 31;
    int g = lane >> 2, tg = lane & 3;
    int wm = warp & 1, wn = warp >> 1;   // 2 m-tiles of 64 rows, 2 n-tiles of 64 cols

    int rL = tid >> 2;            // 0..31
    int c0 = (tid & 3) << 2;      // 0,4,8,12

    const float* aP[4];
    const float* bP[4];
#pragma unroll
    for (int i = 0; i < 4; i++){
        aP[i] = g_act + (size_t)(row0 + rL + 32*i) * FF + c0;
        bP[i] = wd + (size_t)(e*DD + nb + rL + 32*i) * FF + c0;
    }

    float C[4][8][4];
#pragma unroll
    for (int mi = 0; mi < 4; mi++)
#pragma unroll
        for (int ni = 0; ni < 8; ni++)
#pragma unroll
            for (int j = 0; j < 4; j++) C[mi][ni][j] = 0.f;

    float4 aS[4], bS[4];
#pragma unroll
    for (int i = 0; i < 4; i++){
        aS[i] = *reinterpret_cast<const float4*>(aP[i]);
        bS[i] = *reinterpret_cast<const float4*>(bP[i]);
    }
#pragma unroll
    for (int i = 0; i < 4; i++){
        sts_tf4(&sA[0][rL + 32*i][c0], aS[i]);
        sts_tf4(&sB[0][rL + 32*i][c0], bS[i]);
    }
    __syncthreads();

    const int NCH = FF / KC;
    for (int ck = 0; ck < NCH; ck++){
        int cur = ck & 1;
        bool more = (ck + 1) < NCH;
        int koff = (ck + 1) * KC;
        if (more){
#pragma unroll
            for (int i = 0; i < 4; i++){
                aS[i] = *reinterpret_cast<const float4*>(aP[i] + koff);
                bS[i] = *reinterpret_cast<const float4*>(bP[i] + koff);
            }
        }
#pragma unroll
        for (int ks = 0; ks < KC; ks += 8){
            uint32_t a[4][4], b[8][2];
#pragma unroll
            for (int mi = 0; mi < 4; mi++){
                int r0 = wm*64 + mi*16 + g;
                a[mi][0] = sA[cur][r0  ][ks+tg];   a[mi][1] = sA[cur][r0+8][ks+tg];
                a[mi][2] = sA[cur][r0  ][ks+tg+4]; a[mi][3] = sA[cur][r0+8][ks+tg+4];
            }
#pragma unroll
            for (int ni = 0; ni < 8; ni++){
                int br = wn*64 + ni*8 + g;
                b[ni][0] = sB[cur][br][ks+tg]; b[ni][1] = sB[cur][br][ks+tg+4];
            }
#pragma unroll
            for (int mi = 0; mi < 4; mi++)
#pragma unroll
                for (int ni = 0; ni < 8; ni++)
                    mma_tf32(C[mi][ni], a[mi][0],a[mi][1],a[mi][2],a[mi][3], b[ni][0], b[ni][1]);
        }
        if (more){
            int nxt = cur ^ 1;
#pragma unroll
            for (int i = 0; i < 4; i++){
                sts_tf4(&sA[nxt][rL + 32*i][c0], aS[i]);
                sts_tf4(&sB[nxt][rL + 32*i][c0], bS[i]);
            }
            __syncthreads();
        }
    }
    // epilogue: out[t, :] += w * y   (exactly 2 contributions per token -> deterministic)
#pragma unroll
    for (int mi = 0; mi < 4; mi++)
#pragma unroll
        for (int half = 0; half < 2; half++){
            int rl = wm*64 + mi*16 + g + half*8;
            int t  = sTok[rl];
            if (t < 0) continue;
            float wgt = sWt[rl];
#pragma unroll
            for (int ni = 0; ni < 8; ni++){
                int cb = nb + wn*64 + ni*8 + tg*2;
                atomicAdd(&out[(size_t)t*DD + cb    ], wgt * C[mi][ni][half*2+0]);
                atomicAdd(&out[(size_t)t*DD + cb + 1], wgt * C[mi][ni][half*2+1]);
            }
        }
}

// ---------------- launch ----------------
extern "C" void kernel_launch(void* const* d_in, const int* in_sizes, int n_in,
                              void* d_out, int out_size){
    const float* x  = (const float*)d_in[0];   // [T, D]
    const float* gw = (const float*)d_in[1];   // [E, D]
    const float* wg = (const float*)d_in[2];   // [E, F, D]
    const float* wu = (const float*)d_in[3];   // [E, F, D]
    const float* wd = (const float*)d_in[4];   // [E, D, F]
    float* out    = (float*)d_out;             // [T*D] final, then [T*E] logits
    float* logits = out + (size_t)TT * DD;

    cudaMemsetAsync(out, 0, (size_t)TT * DD * sizeof(float));
    router_kernel<<<TT/8, 256>>>(x, gw, logits);
    build_kernel<<<1, 1024>>>();
    gateup_kernel<<<dim3(FF/64, MT), THREADS>>>(x, wg, wu);
    down_kernel  <<<dim3(DD/128, MT), THREADS>>>(wd, out);
}

// round 11
// speedup vs baseline: 1.5528x; 1.0013x over previous
#include <cuda_runtime.h>
#include <cstdint>
#include <math.h>

#define TT 8192
#define DD 2048
#define NE 8
#define FF 1408
#define KC 16              /* k-chunk */
#define SROW 20            /* padded smem row stride (words) = KC + 4 */
#define THREADS 128
#define MAX_ASSIGN 17408   /* 136 * 128 */
#define MT 136             /* row tiles of 128 */

// ---------------- scratch (device globals only; no allocation) ----------------
__device__ int   g_tk_idx[TT*2];
__device__ float g_tk_w[TT*2];
__device__ int   g_offs[NE+1];
__device__ int   g_tok[MAX_ASSIGN];
__device__ int   g_slot[TT*2];
__device__ float g_act[(size_t)MAX_ASSIGN * FF];   // silu(h)*u, fp32
__device__ float g_y[(size_t)MAX_ASSIGN * DD];     // per-assignment down output

// ---------------- helpers ----------------
__device__ __forceinline__ uint32_t f2tf(float f){
    uint32_t u; asm("cvt.rna.tf32.f32 %0, %1;" : "=r"(u) : "f"(f)); return u;
}
__device__ __forceinline__ void mma_tf32(float c[4],
        uint32_t a0, uint32_t a1, uint32_t a2, uint32_t a3,
        uint32_t b0, uint32_t b1){
    asm volatile(
        "mma.sync.aligned.m16n8k8.row.col.f32.tf32.tf32.f32 "
        "{%0,%1,%2,%3}, {%4,%5,%6,%7}, {%8,%9}, {%0,%1,%2,%3};\n"
        : "+f"(c[0]), "+f"(c[1]), "+f"(c[2]), "+f"(c[3])
        : "r"(a0), "r"(a1), "r"(a2), "r"(a3), "r"(b0), "r"(b1));
}
__device__ __forceinline__ void sts_tf4(uint32_t* dst, float4 v){
    *reinterpret_cast<uint4*>(dst) = make_uint4(f2tf(v.x), f2tf(v.y), f2tf(v.z), f2tf(v.w));
}

// ---------------- router: logits, top-2, renormalized weights ----------------
__global__ void router_kernel(const float* __restrict__ x,
                              const float* __restrict__ gw,
                              float* __restrict__ logits){
    int warp = (blockIdx.x * blockDim.x + threadIdx.x) >> 5;
    int lane = threadIdx.x & 31;
    if (warp >= TT) return;
    const float* xr = x + (size_t)warp * DD;
    float acc[NE];
#pragma unroll
    for (int e = 0; e < NE; e++) acc[e] = 0.f;
    for (int c = lane * 4; c < DD; c += 128){
        float4 xv = *reinterpret_cast<const float4*>(xr + c);
#pragma unroll
        for (int e = 0; e < NE; e++){
            float4 gv = *reinterpret_cast<const float4*>(gw + e*DD + c);
            acc[e] += xv.x*gv.x; acc[e] += xv.y*gv.y;
            acc[e] += xv.z*gv.z; acc[e] += xv.w*gv.w;
        }
    }
#pragma unroll
    for (int e = 0; e < NE; e++){
#pragma unroll
        for (int o = 16; o > 0; o >>= 1) acc[e] += __shfl_xor_sync(0xffffffffu, acc[e], o);
    }
    if (lane == 0){
#pragma unroll
        for (int e = 0; e < NE; e++) logits[(size_t)warp*NE + e] = acc[e];
        int i0 = 0; float l0 = acc[0];
#pragma unroll
        for (int e = 1; e < NE; e++) if (acc[e] > l0){ l0 = acc[e]; i0 = e; }
        int i1 = -1; float l1 = -1e30f;
#pragma unroll
        for (int e = 0; e < NE; e++) if (e != i0 && acc[e] > l1){ l1 = acc[e]; i1 = e; }
        float q  = expf(l1 - l0);
        float w0 = 1.f / (1.f + q);
        float w1 = q  / (1.f + q);
        g_tk_idx[warp*2+0] = i0; g_tk_idx[warp*2+1] = i1;
        g_tk_w [warp*2+0] = w0; g_tk_w [warp*2+1] = w1;
    }
}

// ---------------- build per-expert token lists (128-aligned segments) ----------------
__global__ void build_kernel(){
    __shared__ int cnt[NE];
    __shared__ int offs[NE+1];
    __shared__ int cur[NE];
    int tid = threadIdx.x;
    if (tid < NE) cnt[tid] = 0;
    __syncthreads();
    for (int i = tid; i < TT*2; i += blockDim.x) atomicAdd(&cnt[g_tk_idx[i]], 1);
    __syncthreads();
    if (tid == 0){
        int o = 0;
        for (int e = 0; e < NE; e++){ offs[e] = o; cur[e] = o; o += (cnt[e] + 127) & ~127; }
        offs[NE] = o;
        for (int e = 0; e <= NE; e++) g_offs[e] = offs[e];
    }
    __syncthreads();
    for (int i = tid; i < MAX_ASSIGN; i += blockDim.x) g_tok[i] = -1;
    __syncthreads();
    for (int i = tid; i < TT*2; i += blockDim.x){
        int e = g_tk_idx[i];
        int slot = atomicAdd(&cur[e], 1);
        g_tok[slot] = i >> 1;
        g_slot[i] = slot;
    }
}

// ---------------- GEMM 1: gathered x @ {w_gate,w_up}^T -> act = silu(h)*u ----------------
// Block: 128 rows x 64 F-cols; 4 warps; warp tile = 64 rows x 32 F-cols x BOTH h,u.
// Double-buffered smem, register-staged prefetch, one barrier per k-chunk.
__global__ __launch_bounds__(THREADS) void gateup_kernel(const float* __restrict__ x,
        const float* __restrict__ wg, const float* __restrict__ wu){
    __shared__ uint32_t sA [2][128][SROW];
    __shared__ uint32_t sBg[2][64][SROW];
    __shared__ uint32_t sBu[2][64][SROW];
    __shared__ int sTok[128];

    int fb   = blockIdx.x * 64;    // F-column base
    int row0 = blockIdx.y * 128;   // assignment-row tile
    int tid  = threadIdx.x;

    if (row0 >= g_offs[NE]) return;   // fully-dead padding tile

    int e = 0;
#pragma unroll
    for (int i = 0; i < NE-1; i++) if (row0 >= g_offs[i+1]) e = i + 1;

    sTok[tid] = g_tok[row0 + tid];
    __syncthreads();

    int warp = tid >> 5, lane = tid & 31;
    int g = lane >> 2, tg = lane & 3;
    int wm = warp & 1, wn = warp >> 1;    // 2 m-tiles of 64 rows, 2 n-tiles of 32 F-cols

    int rL = tid >> 2;            // 0..31
    int c0 = (tid & 3) << 2;      // 0,4,8,12

    const float* aP[4];
#pragma unroll
    for (int i = 0; i < 4; i++){
        int tok = sTok[rL + 32*i];
        aP[i] = (tok >= 0) ? (x + (size_t)tok * DD + c0) : (const float*)0;
    }
    const float* gP[2];
    const float* uP[2];
#pragma unroll
    for (int i = 0; i < 2; i++){
        gP[i] = wg + (size_t)(e*FF + fb + rL + 32*i) * DD + c0;
        uP[i] = wu + (size_t)(e*FF + fb + rL + 32*i) * DD + c0;
    }

    float hC[4][4][4], uC[4][4][4];
#pragma unroll
    for (int mi = 0; mi < 4; mi++)
#pragma unroll
        for (int ni = 0; ni < 4; ni++)
#pragma unroll
            for (int j = 0; j < 4; j++){ hC[mi][ni][j] = 0.f; uC[mi][ni][j] = 0.f; }

    float4 aS[4], gS[2], uS[2];
#pragma unroll
    for (int i = 0; i < 4; i++)
        aS[i] = aP[i] ? *reinterpret_cast<const float4*>(aP[i]) : make_float4(0.f,0.f,0.f,0.f);
#pragma unroll
    for (int i = 0; i < 2; i++){
        gS[i] = *reinterpret_cast<const float4*>(gP[i]);
        uS[i] = *reinterpret_cast<const float4*>(uP[i]);
    }
#pragma unroll
    for (int i = 0; i < 4; i++) sts_tf4(&sA[0][rL + 32*i][c0], aS[i]);
#pragma unroll
    for (int i = 0; i < 2; i++){
        sts_tf4(&sBg[0][rL + 32*i][c0], gS[i]);
        sts_tf4(&sBu[0][rL + 32*i][c0], uS[i]);
    }
    __syncthreads();

    const int NCH = DD / KC;
    for (int ck = 0; ck < NCH; ck++){
        int cur = ck & 1;
        bool more = (ck + 1) < NCH;
        int koff = (ck + 1) * KC;
        if (more){
#pragma unroll
            for (int i = 0; i < 4; i++)
                aS[i] = aP[i] ? *reinterpret_cast<const float4*>(aP[i] + koff)
                              : make_float4(0.f,0.f,0.f,0.f);
#pragma unroll
            for (int i = 0; i < 2; i++){
                gS[i] = *reinterpret_cast<const float4*>(gP[i] + koff);
                uS[i] = *reinterpret_cast<const float4*>(uP[i] + koff);
            }
        }
#pragma unroll
        for (int ks = 0; ks < KC; ks += 8){
            uint32_t a[4][4];
#pragma unroll
            for (int mi = 0; mi < 4; mi++){
                int r0 = wm*64 + mi*16 + g;
                a[mi][0] = sA[cur][r0  ][ks+tg];   a[mi][1] = sA[cur][r0+8][ks+tg];
                a[mi][2] = sA[cur][r0  ][ks+tg+4]; a[mi][3] = sA[cur][r0+8][ks+tg+4];
            }
#pragma unroll
            for (int ni = 0; ni < 4; ni++){
                int br = wn*32 + ni*8 + g;
                uint32_t bg0 = sBg[cur][br][ks+tg], bg1 = sBg[cur][br][ks+tg+4];
                uint32_t bu0 = sBu[cur][br][ks+tg], bu1 = sBu[cur][br][ks+tg+4];
#pragma unroll
                for (int mi = 0; mi < 4; mi++){
                    mma_tf32(hC[mi][ni], a[mi][0],a[mi][1],a[mi][2],a[mi][3], bg0, bg1);
                    mma_tf32(uC[mi][ni], a[mi][0],a[mi][1],a[mi][2],a[mi][3], bu0, bu1);
                }
            }
        }
        if (more){
            int nxt = cur ^ 1;
#pragma unroll
            for (int i = 0; i < 4; i++) sts_tf4(&sA[nxt][rL + 32*i][c0], aS[i]);
#pragma unroll
            for (int i = 0; i < 2; i++){
                sts_tf4(&sBg[nxt][rL + 32*i][c0], gS[i]);
                sts_tf4(&sBu[nxt][rL + 32*i][c0], uS[i]);
            }
            __syncthreads();
        }
    }
    // epilogue: act = silu(h) * u
#pragma unroll
    for (int mi = 0; mi < 4; mi++)
#pragma unroll
        for (int ni = 0; ni < 4; ni++)
#pragma unroll
            for (int half = 0; half < 2; half++){
                int r    = row0 + wm*64 + mi*16 + g + half*8;
                int fcol = fb + wn*32 + ni*8 + tg*2;
                float h0 = hC[mi][ni][half*2+0], h1 = hC[mi][ni][half*2+1];
                float u0 = uC[mi][ni][half*2+0], u1 = uC[mi][ni][half*2+1];
                float v0 = h0 / (1.f + expf(-h0)) * u0;
                float v1 = h1 / (1.f + expf(-h1)) * u1;
                *reinterpret_cast<float2*>(&g_act[(size_t)r*FF + fcol]) = make_float2(v0, v1);
            }
}

// ---------------- GEMM 2: act @ w_down^T -> y (per-assignment rows, plain STG) ----------------
// Block: 128 rows x 128 D-cols; 4 warps; warp tile = 64 rows x 64 cols.
__global__ __launch_bounds__(THREADS) void down_kernel(const float* __restrict__ wd){
    __shared__ uint32_t sA[2][128][SROW];
    __shared__ uint32_t sB[2][128][SROW];

    int nb   = blockIdx.x * 128;   // D-column base
    int row0 = blockIdx.y * 128;
    int tid  = threadIdx.x;

    if (row0 >= g_offs[NE]) return;   // fully-dead padding tile

    int e = 0;
#pragma unroll
    for (int i = 0; i < NE-1; i++) if (row0 >= g_offs[i+1]) e = i + 1;

    int warp = tid >> 5, lane = tid & 31;
    int g = lane >> 2, tg = lane & 3;
    int wm = warp & 1, wn = warp >> 1;   // 2 m-tiles of 64 rows, 2 n-tiles of 64 cols

    int rL = tid >> 2;            // 0..31
    int c0 = (tid & 3) << 2;      // 0,4,8,12

    const float* aP[4];
    const float* bP[4];
#pragma unroll
    for (int i = 0; i < 4; i++){
        aP[i] = g_act + (size_t)(row0 + rL + 32*i) * FF + c0;
        bP[i] = wd + (size_t)(e*DD + nb + rL + 32*i) * FF + c0;
    }

    float C[4][8][4];
#pragma unroll
    for (int mi = 0; mi < 4; mi++)
#pragma unroll
        for (int ni = 0; ni < 8; ni++)
#pragma unroll
            for (int j = 0; j < 4; j++) C[mi][ni][j] = 0.f;

    float4 aS[4], bS[4];
#pragma unroll
    for (int i = 0; i < 4; i++){
        aS[i] = *reinterpret_cast<const float4*>(aP[i]);
        bS[i] = *reinterpret_cast<const float4*>(bP[i]);
    }
#pragma unroll
    for (int i = 0; i < 4; i++){
        sts_tf4(&sA[0][rL + 32*i][c0], aS[i]);
        sts_tf4(&sB[0][rL + 32*i][c0], bS[i]);
    }
    __syncthreads();

    const int NCH = FF / KC;
    for (int ck = 0; ck < NCH; ck++){
        int cur = ck & 1;
        bool more = (ck + 1) < NCH;
        int koff = (ck + 1) * KC;
        if (more){
#pragma unroll
            for (int i = 0; i < 4; i++){
                aS[i] = *reinterpret_cast<const float4*>(aP[i] + koff);
                bS[i] = *reinterpret_cast<const float4*>(bP[i] + koff);
            }
        }
#pragma unroll
        for (int ks = 0; ks < KC; ks += 8){
            uint32_t a[4][4], b[8][2];
#pragma unroll
            for (int mi = 0; mi < 4; mi++){
                int r0 = wm*64 + mi*16 + g;
                a[mi][0] = sA[cur][r0  ][ks+tg];   a[mi][1] = sA[cur][r0+8][ks+tg];
                a[mi][2] = sA[cur][r0  ][ks+tg+4]; a[mi][3] = sA[cur][r0+8][ks+tg+4];
            }
#pragma unroll
            for (int ni = 0; ni < 8; ni++){
                int br = wn*64 + ni*8 + g;
                b[ni][0] = sB[cur][br][ks+tg]; b[ni][1] = sB[cur][br][ks+tg+4];
            }
#pragma unroll
            for (int mi = 0; mi < 4; mi++)
#pragma unroll
                for (int ni = 0; ni < 8; ni++)
                    mma_tf32(C[mi][ni], a[mi][0],a[mi][1],a[mi][2],a[mi][3], b[ni][0], b[ni][1]);
        }
        if (more){
            int nxt = cur ^ 1;
#pragma unroll
            for (int i = 0; i < 4; i++){
                sts_tf4(&sA[nxt][rL + 32*i][c0], aS[i]);
                sts_tf4(&sB[nxt][rL + 32*i][c0], bS[i]);
            }
            __syncthreads();
        }
    }
    // epilogue: plain STG of per-assignment rows (no atomics)
#pragma unroll
    for (int mi = 0; mi < 4; mi++)
#pragma unroll
        for (int half = 0; half < 2; half++){
            int rl = wm*64 + mi*16 + g + half*8;
            float* yrow = g_y + (size_t)(row0 + rl) * DD + nb;
#pragma unroll
            for (int ni = 0; ni < 8; ni++){
                int cb = wn*64 + ni*8 + tg*2;
                *reinterpret_cast<float2*>(yrow + cb) =
                    make_float2(C[mi][ni][half*2+0], C[mi][ni][half*2+1]);
            }
        }
}

// ---------------- combine: out[t] = w0*y[slot0] + w1*y[slot1] (coalesced) ----------------
__global__ void combine_kernel(float* __restrict__ out){
    int gid = blockIdx.x * 256 + threadIdx.x;   // TT*512 threads, float4 each
    int t = gid >> 9;
    int d = (gid & 511) << 2;
    int s0 = g_slot[2*t], s1 = g_slot[2*t+1];
    float w0 = g_tk_w[2*t], w1 = g_tk_w[2*t+1];
    float4 y0 = *reinterpret_cast<const float4*>(&g_y[(size_t)s0*DD + d]);
    float4 y1 = *reinterpret_cast<const float4*>(&g_y[(size_t)s1*DD + d]);
    float4 r = make_float4(w0*y0.x + w1*y1.x, w0*y0.y + w1*y1.y,
                           w0*y0.z + w1*y1.z, w0*y0.w + w1*y1.w);
    *reinterpret_cast<float4*>(&out[(size_t)t*DD + d]) = r;
}

// ---------------- launch ----------------
extern "C" void kernel_launch(void* const* d_in, const int* in_sizes, int n_in,
                              void* d_out, int out_size){
    const float* x  = (const float*)d_in[0];   // [T, D]
    const float* gw = (const float*)d_in[1];   // [E, D]
    const float* wg = (const float*)d_in[2];   // [E, F, D]
    const float* wu = (const float*)d_in[3];   // [E, F, D]
    const float* wd = (const float*)d_in[4];   // [E, D, F]
    float* out    = (float*)d_out;             // [T*D] final, then [T*E] logits
    float* logits = out + (size_t)TT * DD;

    router_kernel<<<TT/8, 256>>>(x, gw, logits);
    build_kernel<<<1, 1024>>>();
    gateup_kernel<<<dim3(FF/64, MT), THREADS>>>(x, wg, wu);
    down_kernel  <<<dim3(DD/128, MT), THREADS>>>(wd);
    combine_kernel<<<TT*512/256, 256>>>(out);
}

// round 12
// speedup vs baseline: 1.7258x; 1.1114x over previous
#include <cuda_runtime.h>
#include <cstdint>
#include <math.h>

#define TT 8192
#define DD 2048
#define NE 8
#define FF 1408
#define KC 32              /* k-chunk (words) */
#define SROW 36            /* padded smem row stride (words): conflict-free STS+LDS */
#define THREADS 128
#define MAX_ASSIGN 17408   /* 136 * 128 */
#define MT 136             /* row tiles of 128 */

/* dynamic smem word offsets (per stage span = 9216 words = 36864 B, 2 stages = 73728 B) */
#define STG_SPAN 9216
#define OFF_B  4608        /* down: B region */
#define OFF_BG 4608        /* gateup: wg region (64 rows) */
#define OFF_BU 6912        /* gateup: wu region (64 rows) */
#define DYN_BYTES 73728

// ---------------- scratch (device globals only; no allocation) ----------------
__device__ int   g_tk_idx[TT*2];
__device__ float g_tk_w[TT*2];
__device__ int   g_offs[NE+1];
__device__ int   g_tok[MAX_ASSIGN];
__device__ int   g_slot[TT*2];
__device__ float g_act[(size_t)MAX_ASSIGN * FF];   // silu(h)*u, fp32
__device__ float g_y[(size_t)MAX_ASSIGN * DD];     // per-assignment down output

// ---------------- helpers ----------------
__device__ __forceinline__ uint32_t f2tf(float f){
    uint32_t u; asm("cvt.rna.tf32.f32 %0, %1;" : "=r"(u) : "f"(f)); return u;
}
__device__ __forceinline__ void mma_tf32(float c[4],
        uint32_t a0, uint32_t a1, uint32_t a2, uint32_t a3,
        uint32_t b0, uint32_t b1){
    asm volatile(
        "mma.sync.aligned.m16n8k8.row.col.f32.tf32.tf32.f32 "
        "{%0,%1,%2,%3}, {%4,%5,%6,%7}, {%8,%9}, {%0,%1,%2,%3};\n"
        : "+f"(c[0]), "+f"(c[1]), "+f"(c[2]), "+f"(c[3])
        : "r"(a0), "r"(a1), "r"(a2), "r"(a3), "r"(b0), "r"(b1));
}
__device__ __forceinline__ void sts_tf4(uint32_t* dst, float4 v){
    *reinterpret_cast<uint4*>(dst) = make_uint4(f2tf(v.x), f2tf(v.y), f2tf(v.z), f2tf(v.w));
}

// ---------------- router: logits, top-2, renormalized weights ----------------
__global__ void router_kernel(const float* __restrict__ x,
                              const float* __restrict__ gw,
                              float* __restrict__ logits){
    int warp = (blockIdx.x * blockDim.x + threadIdx.x) >> 5;
    int lane = threadIdx.x & 31;
    if (warp >= TT) return;
    const float* xr = x + (size_t)warp * DD;
    float acc[NE];
#pragma unroll
    for (int e = 0; e < NE; e++) acc[e] = 0.f;
    for (int c = lane * 4; c < DD; c += 128){
        float4 xv = *reinterpret_cast<const float4*>(xr + c);
#pragma unroll
        for (int e = 0; e < NE; e++){
            float4 gv = *reinterpret_cast<const float4*>(gw + e*DD + c);
            acc[e] += xv.x*gv.x; acc[e] += xv.y*gv.y;
            acc[e] += xv.z*gv.z; acc[e] += xv.w*gv.w;
        }
    }
#pragma unroll
    for (int e = 0; e < NE; e++){
#pragma unroll
        for (int o = 16; o > 0; o >>= 1) acc[e] += __shfl_xor_sync(0xffffffffu, acc[e], o);
    }
    if (lane == 0){
#pragma unroll
        for (int e = 0; e < NE; e++) logits[(size_t)warp*NE + e] = acc[e];
        int i0 = 0; float l0 = acc[0];
#pragma unroll
        for (int e = 1; e < NE; e++) if (acc[e] > l0){ l0 = acc[e]; i0 = e; }
        int i1 = -1; float l1 = -1e30f;
#pragma unroll
        for (int e = 0; e < NE; e++) if (e != i0 && acc[e] > l1){ l1 = acc[e]; i1 = e; }
        float q  = expf(l1 - l0);
        float w0 = 1.f / (1.f + q);
        float w1 = q  / (1.f + q);
        g_tk_idx[warp*2+0] = i0; g_tk_idx[warp*2+1] = i1;
        g_tk_w [warp*2+0] = w0; g_tk_w [warp*2+1] = w1;
    }
}

// ---------------- build per-expert token lists (128-aligned segments) ----------------
__global__ void build_kernel(){
    __shared__ int cnt[NE];
    __shared__ int offs[NE+1];
    __shared__ int cur[NE];
    int tid = threadIdx.x;
    if (tid < NE) cnt[tid] = 0;
    __syncthreads();
    for (int i = tid; i < TT*2; i += blockDim.x) atomicAdd(&cnt[g_tk_idx[i]], 1);
    __syncthreads();
    if (tid == 0){
        int o = 0;
        for (int e = 0; e < NE; e++){ offs[e] = o; cur[e] = o; o += (cnt[e] + 127) & ~127; }
        offs[NE] = o;
        for (int e = 0; e <= NE; e++) g_offs[e] = offs[e];
    }
    __syncthreads();
    for (int i = tid; i < MAX_ASSIGN; i += blockDim.x) g_tok[i] = -1;
    __syncthreads();
    for (int i = tid; i < TT*2; i += blockDim.x){
        int e = g_tk_idx[i];
        int slot = atomicAdd(&cur[e], 1);
        g_tok[slot] = i >> 1;
        g_slot[i] = slot;
    }
}

// ---------------- GEMM 1: gathered x @ {w_gate,w_up}^T -> act = silu(h)*u ----------------
// Block: 128 rows x 64 F-cols; 4 warps; warp tile = 64 rows x 32 F-cols x BOTH h,u.
// KC=32, SROW=36 (conflict-free), double-buffered dynamic smem, one barrier/chunk.
__global__ __launch_bounds__(THREADS) void gateup_kernel(const float* __restrict__ x,
        const float* __restrict__ wg, const float* __restrict__ wu){
    extern __shared__ uint32_t dyn[];
    __shared__ int sTok[128];

    int fb   = blockIdx.x * 64;    // F-column base
    int row0 = blockIdx.y * 128;   // assignment-row tile
    int tid  = threadIdx.x;

    if (row0 >= g_offs[NE]) return;   // fully-dead padding tile (uniform)

    int e = 0;
#pragma unroll
    for (int i = 0; i < NE-1; i++) if (row0 >= g_offs[i+1]) e = i + 1;

    sTok[tid] = g_tok[row0 + tid];
    __syncthreads();

    int warp = tid >> 5, lane = tid & 31;
    int g = lane >> 2, tg = lane & 3;
    int wm = warp & 1, wn = warp >> 1;    // 2 m-tiles of 64 rows, 2 n-tiles of 32 F-cols

    // loader mapping: 8 threads per row, float4 each -> 16 rows per 128-thread pass
    int rL = tid >> 3;            // 0..15
    int cL = (tid & 7) << 2;      // word col 0,4,...,28

    const float* aP[8];
#pragma unroll
    for (int i = 0; i < 8; i++){
        int tok = sTok[rL + 16*i];
        aP[i] = (tok >= 0) ? (x + (size_t)tok * DD + cL) : (const float*)0;
    }
    const float* gB = wg + (size_t)(e*FF + fb + rL) * DD + cL;   // rows rL+16i for i<4
    const float* uB = wu + (size_t)(e*FF + fb + rL) * DD + cL;

    // smem stage bases (word offsets); thread's STS slots
    // A row r at st*STG_SPAN + r*SROW + cL ; Bg at +OFF_BG ; Bu at +OFF_BU
    float hC[4][4][4], uC[4][4][4];
#pragma unroll
    for (int mi = 0; mi < 4; mi++)
#pragma unroll
        for (int ni = 0; ni < 4; ni++)
#pragma unroll
            for (int j = 0; j < 4; j++){ hC[mi][ni][j] = 0.f; uC[mi][ni][j] = 0.f; }

    // ---- prologue: fill stage 0 ----
    {
        float4 s[8];
#pragma unroll
        for (int i = 0; i < 8; i++)
            s[i] = aP[i] ? *reinterpret_cast<const float4*>(aP[i]) : make_float4(0.f,0.f,0.f,0.f);
#pragma unroll
        for (int i = 0; i < 8; i++)
            sts_tf4(&dyn[(rL + 16*i)*SROW + cL], s[i]);
#pragma unroll
        for (int i = 0; i < 4; i++){
            float4 gv = *reinterpret_cast<const float4*>(gB + (size_t)(16*i)*DD);
            sts_tf4(&dyn[OFF_BG + (rL + 16*i)*SROW + cL], gv);
            float4 uv = *reinterpret_cast<const float4*>(uB + (size_t)(16*i)*DD);
            sts_tf4(&dyn[OFF_BU + (rL + 16*i)*SROW + cL], uv);
        }
    }
    __syncthreads();

    const int NCH = DD / KC;   // 64
    for (int ck = 0; ck < NCH; ck++){
        int cb = (ck & 1) * STG_SPAN;
        int nb_ = ((ck & 1) ^ 1) * STG_SPAN;
        bool more = (ck + 1) < NCH;
        int koff = (ck + 1) * KC;

        // wave 1: prefetch next A
        float4 stA[8];
        if (more){
#pragma unroll
            for (int i = 0; i < 8; i++)
                stA[i] = aP[i] ? *reinterpret_cast<const float4*>(aP[i] + koff)
                               : make_float4(0.f,0.f,0.f,0.f);
        }
        // MMA ks = 0, 8
#pragma unroll
        for (int ks = 0; ks < 16; ks += 8){
            uint32_t a[4][4];
#pragma unroll
            for (int mi = 0; mi < 4; mi++){
                int r0 = (wm*64 + mi*16 + g)*SROW + cb;
                a[mi][0] = dyn[r0 + ks+tg];       a[mi][1] = dyn[r0 + 8*SROW + ks+tg];
                a[mi][2] = dyn[r0 + ks+tg+4];     a[mi][3] = dyn[r0 + 8*SROW + ks+tg+4];
            }
#pragma unroll
            for (int ni = 0; ni < 4; ni++){
                int br = (wn*32 + ni*8 + g)*SROW + cb;
                uint32_t bg0 = dyn[OFF_BG + br + ks+tg], bg1 = dyn[OFF_BG + br + ks+tg+4];
                uint32_t bu0 = dyn[OFF_BU + br + ks+tg], bu1 = dyn[OFF_BU + br + ks+tg+4];
#pragma unroll
                for (int mi = 0; mi < 4; mi++){
                    mma_tf32(hC[mi][ni], a[mi][0],a[mi][1],a[mi][2],a[mi][3], bg0, bg1);
                    mma_tf32(uC[mi][ni], a[mi][0],a[mi][1],a[mi][2],a[mi][3], bu0, bu1);
                }
            }
        }
        // store next A; wave 2: prefetch next B
        float4 stG[4], stU[4];
        if (more){
#pragma unroll
            for (int i = 0; i < 8; i++)
                sts_tf4(&dyn[nb_ + (rL + 16*i)*SROW + cL], stA[i]);
#pragma unroll
            for (int i = 0; i < 4; i++){
                stG[i] = *reinterpret_cast<const float4*>(gB + (size_t)(16*i)*DD + koff);
                stU[i] = *reinterpret_cast<const float4*>(uB + (size_t)(16*i)*DD + koff);
            }
        }
        // MMA ks = 16, 24
#pragma unroll
        for (int ks = 16; ks < 32; ks += 8){
            uint32_t a[4][4];
#pragma unroll
            for (int mi = 0; mi < 4; mi++){
                int r0 = (wm*64 + mi*16 + g)*SROW + cb;
                a[mi][0] = dyn[r0 + ks+tg];       a[mi][1] = dyn[r0 + 8*SROW + ks+tg];
                a[mi][2] = dyn[r0 + ks+tg+4];     a[mi][3] = dyn[r0 + 8*SROW + ks+tg+4];
            }
#pragma unroll
            for (int ni = 0; ni < 4; ni++){
                int br = (wn*32 + ni*8 + g)*SROW + cb;
                uint32_t bg0 = dyn[OFF_BG + br + ks+tg], bg1 = dyn[OFF_BG + br + ks+tg+4];
                uint32_t bu0 = dyn[OFF_BU + br + ks+tg], bu1 = dyn[OFF_BU + br + ks+tg+4];
#pragma unroll
                for (int mi = 0; mi < 4; mi++){
                    mma_tf32(hC[mi][ni], a[mi][0],a[mi][1],a[mi][2],a[mi][3], bg0, bg1);
                    mma_tf32(uC[mi][ni], a[mi][0],a[mi][1],a[mi][2],a[mi][3], bu0, bu1);
                }
            }
        }
        if (more){
#pragma unroll
            for (int i = 0; i < 4; i++){
                sts_tf4(&dyn[nb_ + OFF_BG + (rL + 16*i)*SROW + cL], stG[i]);
                sts_tf4(&dyn[nb_ + OFF_BU + (rL + 16*i)*SROW + cL], stU[i]);
            }
        }
        __syncthreads();
    }
    // epilogue: act = silu(h) * u
#pragma unroll
    for (int mi = 0; mi < 4; mi++)
#pragma unroll
        for (int ni = 0; ni < 4; ni++)
#pragma unroll
            for (int half = 0; half < 2; half++){
                int r    = row0 + wm*64 + mi*16 + g + half*8;
                int fcol = fb + wn*32 + ni*8 + tg*2;
                float h0 = hC[mi][ni][half*2+0], h1 = hC[mi][ni][half*2+1];
                float u0 = uC[mi][ni][half*2+0], u1 = uC[mi][ni][half*2+1];
                float v0 = h0 / (1.f + expf(-h0)) * u0;
                float v1 = h1 / (1.f + expf(-h1)) * u1;
                *reinterpret_cast<float2*>(&g_act[(size_t)r*FF + fcol]) = make_float2(v0, v1);
            }
}

// ---------------- GEMM 2: act @ w_down^T -> y (per-assignment rows, plain STG) ----------------
// Block: 128 rows x 128 D-cols; 4 warps; warp tile = 64 rows x 64 cols.
__global__ __launch_bounds__(THREADS) void down_kernel(const float* __restrict__ wd){
    extern __shared__ uint32_t dyn[];

    int nb   = blockIdx.x * 128;   // D-column base
    int row0 = blockIdx.y * 128;
    int tid  = threadIdx.x;

    if (row0 >= g_offs[NE]) return;   // fully-dead padding tile

    int e = 0;
#pragma unroll
    for (int i = 0; i < NE-1; i++) if (row0 >= g_offs[i+1]) e = i + 1;

    int warp = tid >> 5, lane = tid & 31;
    int g = lane >> 2, tg = lane & 3;
    int wm = warp & 1, wn = warp >> 1;   // 2 m-tiles of 64 rows, 2 n-tiles of 64 cols

    int rL = tid >> 3;            // 0..15
    int cL = (tid & 7) << 2;      // word col 0,4,...,28

    const float* aB = g_act + (size_t)(row0 + rL) * FF + cL;          // rows rL+16i
    const float* bB = wd + (size_t)(e*DD + nb + rL) * FF + cL;

    float C[4][8][4];
#pragma unroll
    for (int mi = 0; mi < 4; mi++)
#pragma unroll
        for (int ni = 0; ni < 8; ni++)
#pragma unroll
            for (int j = 0; j < 4; j++) C[mi][ni][j] = 0.f;

    // ---- prologue ----
    {
#pragma unroll
        for (int i = 0; i < 8; i++){
            float4 v = *reinterpret_cast<const float4*>(aB + (size_t)(16*i)*FF);
            sts_tf4(&dyn[(rL + 16*i)*SROW + cL], v);
        }
#pragma unroll
        for (int i = 0; i < 8; i++){
            float4 v = *reinterpret_cast<const float4*>(bB + (size_t)(16*i)*FF);
            sts_tf4(&dyn[OFF_B + (rL + 16*i)*SROW + cL], v);
        }
    }
    __syncthreads();

    const int NCH = FF / KC;   // 44
    for (int ck = 0; ck < NCH; ck++){
        int cb = (ck & 1) * STG_SPAN;
        int nb_ = ((ck & 1) ^ 1) * STG_SPAN;
        bool more = (ck + 1) < NCH;
        int koff = (ck + 1) * KC;

        float4 stA[8];
        if (more){
#pragma unroll
            for (int i = 0; i < 8; i++)
                stA[i] = *reinterpret_cast<const float4*>(aB + (size_t)(16*i)*FF + koff);
        }
#pragma unroll
        for (int ks = 0; ks < 16; ks += 8){
            uint32_t a[4][4], b[8][2];
#pragma unroll
            for (int mi = 0; mi < 4; mi++){
                int r0 = (wm*64 + mi*16 + g)*SROW + cb;
                a[mi][0] = dyn[r0 + ks+tg];       a[mi][1] = dyn[r0 + 8*SROW + ks+tg];
                a[mi][2] = dyn[r0 + ks+tg+4];     a[mi][3] = dyn[r0 + 8*SROW + ks+tg+4];
            }
#pragma unroll
            for (int ni = 0; ni < 8; ni++){
                int br = (wn*64 + ni*8 + g)*SROW + cb;
                b[ni][0] = dyn[OFF_B + br + ks+tg]; b[ni][1] = dyn[OFF_B + br + ks+tg+4];
            }
#pragma unroll
            for (int mi = 0; mi < 4; mi++)
#pragma unroll
                for (int ni = 0; ni < 8; ni++)
                    mma_tf32(C[mi][ni], a[mi][0],a[mi][1],a[mi][2],a[mi][3], b[ni][0], b[ni][1]);
        }
        float4 stB[8];
        if (more){
#pragma unroll
            for (int i = 0; i < 8; i++)
                sts_tf4(&dyn[nb_ + (rL + 16*i)*SROW + cL], stA[i]);
#pragma unroll
            for (int i = 0; i < 8; i++)
                stB[i] = *reinterpret_cast<const float4*>(bB + (size_t)(16*i)*FF + koff);
        }
#pragma unroll
        for (int ks = 16; ks < 32; ks += 8){
            uint32_t a[4][4], b[8][2];
#pragma unroll
            for (int mi = 0; mi < 4; mi++){
                int r0 = (wm*64 + mi*16 + g)*SROW + cb;
                a[mi][0] = dyn[r0 + ks+tg];       a[mi][1] = dyn[r0 + 8*SROW + ks+tg];
                a[mi][2] = dyn[r0 + ks+tg+4];     a[mi][3] = dyn[r0 + 8*SROW + ks+tg+4];
            }
#pragma unroll
            for (int ni = 0; ni < 8; ni++){
                int br = (wn*64 + ni*8 + g)*SROW + cb;
                b[ni][0] = dyn[OFF_B + br + ks+tg]; b[ni][1] = dyn[OFF_B + br + ks+tg+4];
            }
#pragma unroll
            for (int mi = 0; mi < 4; mi++)
#pragma unroll
                for (int ni = 0; ni < 8; ni++)
                    mma_tf32(C[mi][ni], a[mi][0],a[mi][1],a[mi][2],a[mi][3], b[ni][0], b[ni][1]);
        }
        if (more){
#pragma unroll
            for (int i = 0; i < 8; i++)
                sts_tf4(&dyn[nb_ + OFF_B + (rL + 16*i)*SROW + cL], stB[i]);
        }
        __syncthreads();
    }
    // epilogue: plain STG of per-assignment rows (no atomics)
#pragma unroll
    for (int mi = 0; mi < 4; mi++)
#pragma unroll
        for (int half = 0; half < 2; half++){
            int rl = wm*64 + mi*16 + g + half*8;
            float* yrow = g_y + (size_t)(row0 + rl) * DD + nb;
#pragma unroll
            for (int ni = 0; ni < 8; ni++){
                int cb2 = wn*64 + ni*8 + tg*2;
                *reinterpret_cast<float2*>(yrow + cb2) =
                    make_float2(C[mi][ni][half*2+0], C[mi][ni][half*2+1]);
            }
        }
}

// ---------------- combine: out[t] = w0*y[slot0] + w1*y[slot1] (coalesced) ----------------
__global__ void combine_kernel(float* __restrict__ out){
    int gid = blockIdx.x * 256 + threadIdx.x;   // TT*512 threads, float4 each
    int t = gid >> 9;
    int d = (gid & 511) << 2;
    int s0 = g_slot[2*t], s1 = g_slot[2*t+1];
    float w0 = g_tk_w[2*t], w1 = g_tk_w[2*t+1];
    float4 y0 = *reinterpret_cast<const float4*>(&g_y[(size_t)s0*DD + d]);
    float4 y1 = *reinterpret_cast<const float4*>(&g_y[(size_t)s1*DD + d]);
    float4 r = make_float4(w0*y0.x + w1*y1.x, w0*y0.y + w1*y1.y,
                           w0*y0.z + w1*y1.z, w0*y0.w + w1*y1.w);
    *reinterpret_cast<float4*>(&out[(size_t)t*DD + d]) = r;
}

// ---------------- launch ----------------
extern "C" void kernel_launch(void* const* d_in, const int* in_sizes, int n_in,
                              void* d_out, int out_size){
    const float* x  = (const float*)d_in[0];   // [T, D]
    const float* gw = (const float*)d_in[1];   // [E, D]
    const float* wg = (const float*)d_in[2];   // [E, F, D]
    const float* wu = (const float*)d_in[3];   // [E, F, D]
    const float* wd = (const float*)d_in[4];   // [E, D, F]
    float* out    = (float*)d_out;             // [T*D] final, then [T*E] logits
    float* logits = out + (size_t)TT * DD;

    static int attr_done = 0;
    if (!attr_done){
        cudaFuncSetAttribute(gateup_kernel, cudaFuncAttributeMaxDynamicSharedMemorySize, DYN_BYTES);
        cudaFuncSetAttribute(down_kernel,   cudaFuncAttributeMaxDynamicSharedMemorySize, DYN_BYTES);
        attr_done = 1;
    }

    router_kernel<<<TT/8, 256>>>(x, gw, logits);
    build_kernel<<<1, 1024>>>();
    gateup_kernel<<<dim3(FF/64, MT), THREADS, DYN_BYTES>>>(x, wg, wu);
    down_kernel  <<<dim3(DD/128, MT), THREADS, DYN_BYTES>>>(wd);
    combine_kernel<<<TT*512/256, 256>>>(out);
}